// round 13
// baseline (speedup 1.0000x reference)
#include <cuda_runtime.h>
#include <cuda_bf16.h>
#include <cuda_fp16.h>
#include <stdint.h>
#include <math.h>

using u32 = unsigned int;
using u64 = unsigned long long;
using bf16 = __nv_bfloat16;
using bf162 = __nv_bfloat162;

// ---------------- problem constants ----------------
constexpr int BATCH = 8;
constexpr int HWP   = 224;
constexpr int LPIX  = HWP * HWP;      // 50176
constexpr int DIM   = 192;
constexpr int NH    = 6;
constexpr int HD    = 32;
constexpr int DFF   = 768;
constexpr int WSZ   = 7;
constexpr int SHF   = 3;
constexpr int NTOK  = 49;
constexpr int NWTOT = 8192;
constexpr int MTOK  = BATCH * LPIX;   // 401408

// ---------------- scratch globals ----------------
__device__ bf16  g_qkv[(size_t)MTOK * 3 * DIM];
__device__ bf16  g_att[(size_t)MTOK * DIM];
__device__ float g_y  [(size_t)MTOK * DIM];       // residual stream (fp32)
__device__ bf16  g_wt [442368];                   // transposed bf16 weights
__device__ float g_bias[4 * 6 * 64 * 56];         // bias+mask per window type

constexpr int WT_QKV = 0;        // [576][192]
constexpr int WT_PRJ = 110592;   // [192][192]
constexpr int WT_M1  = 147456;   // [768][192]
constexpr int WT_M2  = 294912;   // [192][768]

// g_h: LN1 output, then (after QKV consumed it) LN2 output (bf16 [MTOK][192])
__device__ bf16  g_h  [(size_t)MTOK * DIM];

// ---------------- PTX helpers ----------------
__device__ __forceinline__ void mma16(float* c, const u32* a, const u32* b) {
    asm volatile(
        "mma.sync.aligned.m16n8k16.row.col.f32.bf16.bf16.f32 "
        "{%0,%1,%2,%3}, {%4,%5,%6,%7}, {%8,%9}, {%0,%1,%2,%3};"
        : "+f"(c[0]), "+f"(c[1]), "+f"(c[2]), "+f"(c[3])
        : "r"(a[0]), "r"(a[1]), "r"(a[2]), "r"(a[3]), "r"(b[0]), "r"(b[1]));
}
__device__ __forceinline__ void mma16h(float* c, const u32* a, const u32* b) {
    asm volatile(
        "mma.sync.aligned.m16n8k16.row.col.f32.f16.f16.f32 "
        "{%0,%1,%2,%3}, {%4,%5,%6,%7}, {%8,%9}, {%0,%1,%2,%3};"
        : "+f"(c[0]), "+f"(c[1]), "+f"(c[2]), "+f"(c[3])
        : "r"(a[0]), "r"(a[1]), "r"(a[2]), "r"(a[3]), "r"(b[0]), "r"(b[1]));
}
__device__ __forceinline__ void ldsm_x4(u32* r, u32 addr) {
    asm volatile("ldmatrix.sync.aligned.m8n8.x4.shared.b16 {%0,%1,%2,%3}, [%4];"
        : "=r"(r[0]), "=r"(r[1]), "=r"(r[2]), "=r"(r[3]) : "r"(addr));
}
__device__ __forceinline__ void ldsm_x2(u32* r, u32 addr) {
    asm volatile("ldmatrix.sync.aligned.m8n8.x2.shared.b16 {%0,%1}, [%2];"
        : "=r"(r[0]), "=r"(r[1]) : "r"(addr));
}
__device__ __forceinline__ u32 smem_u32(const void* p) {
    u32 a; asm("{ .reg .u64 t; cvta.to.shared.u64 t, %1; cvt.u32.u64 %0, t; }" : "=r"(a) : "l"(p));
    return a;
}
__device__ __forceinline__ void cpa16(u32 saddr, const void* gaddr) {
    asm volatile("cp.async.cg.shared.global [%0], [%1], 16;" :: "r"(saddr), "l"(gaddr));
}
#define CP_COMMIT() asm volatile("cp.async.commit_group;" ::: "memory")
#define CP_WAIT2()  asm volatile("cp.async.wait_group 2;" ::: "memory")
#define CP_WAIT1()  asm volatile("cp.async.wait_group 1;" ::: "memory")
#define CP_WAIT0()  asm volatile("cp.async.wait_group 0;" ::: "memory")

// fast gelu: tanh form
__device__ __forceinline__ float gelu_f(float v) {
    float u = v * (0.7978845608028654f + 0.035677408136300125f * v * v);
    float th; asm("tanh.approx.f32 %0, %1;" : "=f"(th) : "f"(u));
    return 0.5f * v * (1.f + th);
}

// reverse window-partition + roll(+3)
__device__ __forceinline__ size_t scat_row(int m) {
    int bw = m / NTOK, n = m - bw * NTOK;
    int bb = bw >> 10, wdx = bw & 1023;
    int wi = wdx >> 5, wj = wdx & 31;
    int r = n / WSZ, cc = n - r * WSZ;
    int pi = wi * WSZ + r + SHF; if (pi >= HWP) pi -= HWP;
    int pj = wj * WSZ + cc + SHF; if (pj >= HWP) pj -= HWP;
    return ((size_t)bb * LPIX + (size_t)pi * HWP + pj) * DIM;
}

// ---------------- all weight transposes in one launch --------------------
__global__ void k_trall(const float* __restrict__ qkv_w, const float* __restrict__ proj_w,
                        const float* __restrict__ w1, const float* __restrict__ w2,
                        bf16* __restrict__ wt) {
    int i = blockIdx.x * 256 + threadIdx.x;
    if (i < 110592) {
        int k = i / 576, n = i - k * 576;
        wt[WT_QKV + n * 192 + k] = __float2bfloat16(qkv_w[i]);
    } else if (i < 147456) {
        int j = i - 110592; int k = j / 192, n = j - k * 192;
        wt[WT_PRJ + n * 192 + k] = __float2bfloat16(proj_w[j]);
    } else if (i < 294912) {
        int j = i - 147456; int k = j / 768, n = j - k * 768;
        wt[WT_M1 + n * 192 + k] = __float2bfloat16(w1[j]);
    } else if (i < 442368) {
        int j = i - 294912; int k = j / 192, n = j - k * 192;
        wt[WT_M2 + n * 768 + k] = __float2bfloat16(w2[j]);
    }
}

// ---------------- bias+mask tables: [type][head][64][56] -----------------
__global__ void k_bias(const float* __restrict__ rpb) {
    int idx = blockIdx.x * 256 + threadIdx.x;
    if (idx >= 4 * 6 * 64 * 56) return;
    int n  = idx % 56;
    int m  = (idx / 56) % 64;
    int h  = (idx / (56 * 64)) % 6;
    int tt = idx / (56 * 64 * 6);
    float v;
    if (m >= NTOK || n >= NTOK) {
        v = -1e30f;
    } else {
        int rm = m / WSZ, cm = m % WSZ, rn = n / WSZ, cn = n % WSZ;
        v = rpb[((rm - rn + 6) * 13 + (cm - cn + 6)) * NH + h];
        int bi = tt >> 1, bj = tt & 1;
        int hrm = bi ? (rm < 4 ? 1 : 2) : 0;
        int hrn = bi ? (rn < 4 ? 1 : 2) : 0;
        int gcm = bj ? (cm < 4 ? 1 : 2) : 0;
        int gcn = bj ? (cn < 4 ? 1 : 2) : 0;
        if (hrm != hrn || gcm != gcn) v -= 100.f;
    }
    g_bias[idx] = v;
}

// ---------------- LayerNorm1 (one warp / token), bf16 outputs ----------
__global__ void __launch_bounds__(256) k_ln(const float* __restrict__ xin,
                                            const float* __restrict__ w,
                                            const float* __restrict__ b) {
    int warp = threadIdx.x >> 5, lane = threadIdx.x & 31;
    int m = blockIdx.x * 8 + warp;
    int bw = m / NTOK, n = m - bw * NTOK;
    int bb = bw >> 10, wdx = bw & 1023;
    int wi = wdx >> 5, wj = wdx & 31;
    int r = n / WSZ, c = n - r * WSZ;
    int pi = wi * WSZ + r + SHF; if (pi >= HWP) pi -= HWP;
    int pj = wj * WSZ + c + SHF; if (pj >= HWP) pj -= HWP;
    const float* src = xin + ((size_t)bb * LPIX + (size_t)pi * HWP + pj) * DIM;
    bf16* dst = g_h + (size_t)m * DIM;

    float v[6]; float s = 0.f, s2 = 0.f;
#pragma unroll
    for (int j = 0; j < 6; j++) {
        v[j] = src[lane + 32 * j];
        s += v[j]; s2 += v[j] * v[j];
    }
#pragma unroll
    for (int o = 16; o > 0; o >>= 1) {
        s  += __shfl_xor_sync(0xffffffffu, s,  o);
        s2 += __shfl_xor_sync(0xffffffffu, s2, o);
    }
    float mu  = s * (1.f / DIM);
    float var = s2 * (1.f / DIM) - mu * mu;
    float rs  = rsqrtf(var + 1e-5f);
#pragma unroll
    for (int j = 0; j < 6; j++) {
        int kk = lane + 32 * j;
        dst[kk] = __float2bfloat16((v[j] - mu) * rs * __ldg(&w[kk]) + __ldg(&b[kk]));
    }
}

// ---------------- QKV GEMM: 12 warps (4m x 3n), warp tile 32x32 ----------
constexpr int PITCH2 = 200;
constexpr int MMA_SMEM = (128 + 96) * PITCH2 * 2;   // 89,600 B

__global__ void __launch_bounds__(384, 2) k_mma(const bf16* __restrict__ WT,
                                                const float* __restrict__ bias) {
    extern __shared__ bf16 smb[];
    bf16* As = smb;                      // [128][200]
    bf16* Bs = smb + 128 * PITCH2;       // [96][200]

    const int t = threadIdx.x;
    const int n0 = blockIdx.x * 96;
    const int m0 = blockIdx.y * 128;
    const bf16* A = g_h;

    const int lane = t & 31, w = t >> 5;
    const int mw = (w / 3) * 32;         // 0,32,64,96
    const int nw = (w % 3) * 32;         // 0,32,64
    const int g = lane >> 2, tg = lane & 3;

    const u32 uA = smem_u32(As), uB = smem_u32(Bs);
    const u32 aq  = uA + (u32)(((mw + (lane & 15)) * PITCH2 + (lane >> 4) * 8) * 2);
    const int rb  = ((lane >> 4) << 3) + (lane & 7);
    const int kbo = ((lane >> 3) & 1) * 8;
    const u32 bq0 = uB + (u32)(((nw + rb) * PITCH2 + kbo) * 2);
    const u32 bq1 = uB + (u32)(((nw + 16 + rb) * PITCH2 + kbo) * 2);

    float acc[2][4][4] = {};

    auto stage = [&](int s) {
        const int col = (s % 3) * 64;
        for (int id = t; id < 1792; id += 384) {
            if (id < 1024) {                         // A: 128 rows x 8 f4
                int row = id >> 3, f = id & 7;
                cpa16(uA + (u32)((row * PITCH2 + col + f * 8) * 2),
                      A + (size_t)(m0 + row) * 192 + s * 64 + f * 8);
            } else {                                 // B: 96 rows x 8 f4
                int id2 = id - 1024;
                int row = id2 >> 3, f = id2 & 7;
                cpa16(uB + (u32)((row * PITCH2 + col + f * 8) * 2),
                      WT + (size_t)(n0 + row) * 192 + s * 64 + f * 8);
            }
        }
        CP_COMMIT();
    };

    stage(0); stage(1); stage(2);

#pragma unroll 1
    for (int s = 0; s < 3; s++) {
        int rem = 2 - s;
        if (rem >= 2) { CP_WAIT2(); } else if (rem == 1) { CP_WAIT1(); } else { CP_WAIT0(); }
        __syncthreads();
        const int koff = (s % 3) * 64;
#pragma unroll
        for (int ks = 0; ks < 4; ks++) {
            const u32 kb2 = (u32)((koff + ks * 16) * 2);
            u32 a[2][4], b[8];
            ldsm_x4(a[0], aq + kb2);
            ldsm_x4(a[1], aq + (u32)(16 * PITCH2 * 2) + kb2);
            ldsm_x4(b,     bq0 + kb2);
            ldsm_x4(b + 4, bq1 + kb2);
#pragma unroll
            for (int i = 0; i < 2; i++)
#pragma unroll
                for (int j = 0; j < 4; j++)
                    mma16(acc[i][j], a[i], b + 2 * j);
        }
        __syncthreads();
    }

#pragma unroll
    for (int i = 0; i < 2; i++) {
        int r0 = m0 + mw + i * 16 + g;
#pragma unroll
        for (int half = 0; half < 2; half++) {
            int m = r0 + half * 8;
#pragma unroll
            for (int j = 0; j < 4; j++) {
                int col = n0 + nw + j * 8 + 2 * tg;
                float v0 = acc[i][j][half * 2 + 0] + __ldg(&bias[col]);
                float v1 = acc[i][j][half * 2 + 1] + __ldg(&bias[col + 1]);
                *(bf162*)(g_qkv + (size_t)m * 576 + col) =
                    __float22bfloat162_rn(make_float2(v0, v1));
            }
        }
    }
}

// ---------------- fused proj + residual + LN2 ----------------------------
constexpr int PRJ_SMEM = (64 + 192) * PITCH2 * 2;   // 102,400 B

__global__ void __launch_bounds__(256, 2) k_proj(const bf16* __restrict__ WT,
                                                 const float* __restrict__ bias,
                                                 const float* __restrict__ x,
                                                 const float* __restrict__ n2w,
                                                 const float* __restrict__ n2b) {
    extern __shared__ bf16 smb[];
    bf16* As = smb;                      // [64][200]
    bf16* Bs = smb + 64 * PITCH2;        // [192][200]

    const int t = threadIdx.x;
    const int m0 = blockIdx.x * 64;

    const int lane = t & 31, w = t >> 5;
    const int nw = w * 24;               // 8 warps x 24 = 192
    const int g = lane >> 2, tg = lane & 3;

    const u32 uA = smem_u32(As), uB = smem_u32(Bs);
    const u32 aq  = uA + (u32)(((lane & 15) * PITCH2 + (lane >> 4) * 8) * 2);
    const int rb  = ((lane >> 4) << 3) + (lane & 7);
    const int kbo = ((lane >> 3) & 1) * 8;
    const u32 bq4 = uB + (u32)(((nw + rb) * PITCH2 + kbo) * 2);
    const u32 bq2 = uB + (u32)(((nw + 16 + rb) * PITCH2 + kbo) * 2);

    float acc[4][3][4] = {};

    auto stage = [&](int s) {
        const int col = (s % 3) * 64;
#pragma unroll
        for (int it = 0; it < 8; it++) {
            int id = t + it * 256;
            if (id < 512) {
                int row = id >> 3, f = id & 7;
                cpa16(uA + (u32)((row * PITCH2 + col + f * 8) * 2),
                      g_att + (size_t)(m0 + row) * 192 + s * 64 + f * 8);
            } else {
                int id2 = id - 512;
                int row = id2 >> 3, f = id2 & 7;
                cpa16(uB + (u32)((row * PITCH2 + col + f * 8) * 2),
                      WT + (size_t)row * 192 + s * 64 + f * 8);
            }
        }
        CP_COMMIT();
    };

    stage(0); stage(1); stage(2);

#pragma unroll 1
    for (int s = 0; s < 3; s++) {
        int rem = 2 - s;
        if (rem >= 2) { CP_WAIT2(); } else if (rem == 1) { CP_WAIT1(); } else { CP_WAIT0(); }
        __syncthreads();
        const int koff = (s % 3) * 64;
#pragma unroll
        for (int ks = 0; ks < 4; ks++) {
            const u32 kb2 = (u32)((koff + ks * 16) * 2);
            u32 a[4][4], b[6];
#pragma unroll
            for (int i = 0; i < 4; i++)
                ldsm_x4(a[i], aq + (u32)(i * 16 * PITCH2 * 2) + kb2);
            ldsm_x4(b, bq4 + kb2);
            ldsm_x2(b + 4, bq2 + kb2);
#pragma unroll
            for (int i = 0; i < 4; i++) {
                mma16(acc[i][0], a[i], b);
                mma16(acc[i][1], a[i], b + 2);
                mma16(acc[i][2], a[i], b + 4);
            }
        }
        __syncthreads();
    }

    // ---- epilogue: y = acc + bias + x; row reduce; LN; dual store ----
    float* red = (float*)smb;            // [64][8 warps][2] = 4KB
    float* murs = red + 1024;            // [64][2]

#pragma unroll
    for (int i = 0; i < 4; i++) {
#pragma unroll
        for (int half = 0; half < 2; half++) {
            int row = i * 16 + g + 8 * half;
            size_t srow = scat_row(m0 + row);
            float s = 0.f, s2 = 0.f;
#pragma unroll
            for (int j = 0; j < 3; j++) {
                int col = nw + j * 8 + 2 * tg;
                float2 xr = *(const float2*)(x + srow + col);
                float v0 = acc[i][j][half * 2 + 0] + __ldg(&bias[col]) + xr.x;
                float v1 = acc[i][j][half * 2 + 1] + __ldg(&bias[col + 1]) + xr.y;
                acc[i][j][half * 2 + 0] = v0;
                acc[i][j][half * 2 + 1] = v1;
                s += v0 + v1; s2 += v0 * v0 + v1 * v1;
            }
            s  += __shfl_xor_sync(0xffffffffu, s, 1);
            s  += __shfl_xor_sync(0xffffffffu, s, 2);
            s2 += __shfl_xor_sync(0xffffffffu, s2, 1);
            s2 += __shfl_xor_sync(0xffffffffu, s2, 2);
            if (tg == 0) {
                red[row * 16 + w * 2 + 0] = s;
                red[row * 16 + w * 2 + 1] = s2;
            }
        }
    }
    __syncthreads();
    if (t < 64) {
        float s = 0.f, s2 = 0.f;
#pragma unroll
        for (int w8 = 0; w8 < 8; w8++) {
            s  += red[t * 16 + w8 * 2 + 0];
            s2 += red[t * 16 + w8 * 2 + 1];
        }
        float mu = s * (1.f / DIM);
        float var = s2 * (1.f / DIM) - mu * mu;
        murs[t * 2 + 0] = mu;
        murs[t * 2 + 1] = rsqrtf(var + 1e-5f);
    }
    __syncthreads();

#pragma unroll
    for (int i = 0; i < 4; i++) {
#pragma unroll
        for (int half = 0; half < 2; half++) {
            int row = i * 16 + g + 8 * half;
            size_t srow = scat_row(m0 + row);
            float mu = murs[row * 2 + 0], rs = murs[row * 2 + 1];
#pragma unroll
            for (int j = 0; j < 3; j++) {
                int col = nw + j * 8 + 2 * tg;
                float v0 = acc[i][j][half * 2 + 0];
                float v1 = acc[i][j][half * 2 + 1];
                *(float2*)(g_y + srow + col) = make_float2(v0, v1);
                float a0 = (v0 - mu) * rs * __ldg(&n2w[col]) + __ldg(&n2b[col]);
                float a1 = (v1 - mu) * rs * __ldg(&n2w[col + 1]) + __ldg(&n2b[col + 1]);
                *(bf162*)(g_h + srow + col) = __float22bfloat162_rn(make_float2(a0, a1));
            }
        }
    }
}

// ---------------- fused MLP ----------------
constexpr int MLP_SMEM = 196096;   // bytes

__global__ void __launch_bounds__(512, 1) k_mlp(const bf16* __restrict__ W1T,
                                                const bf16* __restrict__ W2T,
                                                const float* __restrict__ b1,
                                                const float* __restrict__ b2,
                                                float* __restrict__ dout) {
    extern __shared__ bf16 smb[];
    bf16* Asm = smb;                 // [128][200]
    bf16* Hs  = smb + 25600;         // [128][104]
    bf16* W1s = smb + 38912;         // [96][200]
    bf16* W2s = smb + 58112;         // [2][192][104]

    const int t = threadIdx.x;
    const int m0 = blockIdx.x * 128;
    const int lane = t & 31, w = t >> 5;
    const int mwp = (w >> 2) * 32;
    const int nwA = (w & 3) * 24;
    const int nwB = (w & 3) * 48;
    const int g = lane >> 2, tg = lane & 3;

    const u32 uA = smem_u32(Asm), uH = smem_u32(Hs);
    const u32 uW1 = smem_u32(W1s), uW2 = smem_u32(W2s);

    const u32 aqA = uA + (u32)(((mwp + (lane & 15)) * 200 + (lane >> 4) * 8) * 2);
    const u32 aqB = uH + (u32)(((mwp + (lane & 15)) * 104 + (lane >> 4) * 8) * 2);
    const int rb  = ((lane >> 4) << 3) + (lane & 7);
    const int kbo = ((lane >> 3) & 1) * 8;
    const u32 bq4A = uW1 + (u32)(((nwA + rb) * 200 + kbo) * 2);
    const u32 bq2A = uW1 + (u32)(((nwA + 16 + rb) * 200 + kbo) * 2);

    float accB[2][6][4] = {};

    auto stage_A = [&] {
        for (int id = t; id < 3072; id += 512) {
            int row = id / 24, f = id - row * 24;
            cpa16(uA + (u32)((row * 200 + f * 8) * 2),
                  g_h + (size_t)(m0 + row) * DIM + f * 8);
        }
    };
    auto stage_W1 = [&](int c) {
        for (int id = t; id < 2304; id += 512) {
            int row = id / 24, f = id - row * 24;
            cpa16(uW1 + (u32)((row * 200 + f * 8) * 2),
                  W1T + (size_t)(96 * c + row) * DIM + f * 8);
        }
    };
    auto stage_W2 = [&](int c) {
        const u32 base = uW2 + (u32)((c & 1) * 19968 * 2);
        for (int id = t; id < 2304; id += 512) {
            int row = id / 12, f = id - row * 12;
            cpa16(base + (u32)((row * 104 + f * 8) * 2),
                  W2T + (size_t)row * DFF + 96 * c + f * 8);
        }
    };

    stage_A(); stage_W1(0); stage_W2(0); CP_COMMIT();
    stage_W2(1); CP_COMMIT();

#pragma unroll 1
    for (int c = 0; c < 8; c++) {
        if (c < 7) { CP_WAIT1(); } else { CP_WAIT0(); }
        __syncthreads();

        float acc2[2][3][4] = {};
#pragma unroll
        for (int ks = 0; ks < 12; ks++) {
            const u32 kb = (u32)(ks * 32);
            u32 a[2][4], b[6];
            ldsm_x4(a[0], aqA + kb);
            ldsm_x4(a[1], aqA + (u32)(16 * 200 * 2) + kb);
            ldsm_x4(b, bq4A + kb);
            ldsm_x2(b + 4, bq2A + kb);
#pragma unroll
            for (int i = 0; i < 2; i++) {
                mma16(acc2[i][0], a[i], b);
                mma16(acc2[i][1], a[i], b + 2);
                mma16(acc2[i][2], a[i], b + 4);
            }
        }
        __syncthreads();

        if (c + 1 < 8) { stage_W1(c + 1); CP_COMMIT(); }

#pragma unroll
        for (int i = 0; i < 2; i++)
#pragma unroll
            for (int half = 0; half < 2; half++) {
                int row = mwp + i * 16 + g + half * 8;
#pragma unroll
                for (int j = 0; j < 3; j++) {
                    int col = nwA + j * 8 + 2 * tg;
                    int gcol = c * 96 + col;
                    float v0 = acc2[i][j][half * 2 + 0] + __ldg(&b1[gcol]);
                    float v1 = acc2[i][j][half * 2 + 1] + __ldg(&b1[gcol + 1]);
                    *(bf162*)(Hs + row * 104 + col) =
                        __float22bfloat162_rn(make_float2(gelu_f(v0), gelu_f(v1)));
                }
            }
        __syncthreads();
        CP_WAIT2();

        const u32 w2b = uW2 + (u32)((c & 1) * 19968 * 2);
#pragma unroll
        for (int ks = 0; ks < 6; ks++) {
            const u32 kb = (u32)(ks * 32);
            u32 a[2][4], b[12];
            ldsm_x4(a[0], aqB + kb);
            ldsm_x4(a[1], aqB + (u32)(16 * 104 * 2) + kb);
#pragma unroll
            for (int j2 = 0; j2 < 3; j2++)
                ldsm_x4(b + j2 * 4,
                        w2b + (u32)(((nwB + j2 * 16 + rb) * 104 + kbo) * 2) + kb);
#pragma unroll
            for (int i = 0; i < 2; i++)
#pragma unroll
                for (int jn = 0; jn < 6; jn++)
                    mma16(accB[i][jn], a[i], b + jn * 2);
        }
        __syncthreads();

        if (c + 2 < 8) { stage_W2(c + 2); CP_COMMIT(); }
    }

#pragma unroll
    for (int i = 0; i < 2; i++)
#pragma unroll
        for (int half = 0; half < 2; half++) {
            int m = m0 + mwp + i * 16 + g + half * 8;
#pragma unroll
            for (int jn = 0; jn < 6; jn++) {
                int col = nwB + jn * 8 + 2 * tg;
                const float* yy = g_y + (size_t)m * DIM + col;
                float v0 = accB[i][jn][half * 2 + 0] + __ldg(&b2[col]) + yy[0];
                float v1 = accB[i][jn][half * 2 + 1] + __ldg(&b2[col + 1]) + yy[1];
                *(float2*)(dout + (size_t)m * DIM + col) = make_float2(v0, v1);
            }
        }
}

// ---------------- tensor-core windowed attention -------------------------
constexpr int ATT_SMEM = 85248;

__global__ void __launch_bounds__(384) k_attn() {
    extern __shared__ bf16 smb[];
    bf16*  Qs  = smb;
    bf16*  Ks  = smb + 15360;
    __half* Vts = (__half*)(smb + 28800);

    const int bw = blockIdx.x, t = threadIdx.x;
    const int wdx = bw & 1023, wi = wdx >> 5, wj = wdx & 31;
    const int tt = ((wi == 31) ? 2 : 0) + ((wj == 31) ? 1 : 0);
    const float* Tb = g_bias + tt * (6 * 64 * 56);
    const bf16* base = g_qkv + (size_t)bw * NTOK * 576;

    for (int i = t; i < ATT_SMEM / 16; i += 384)
        ((uint4*)smb)[i] = make_uint4(0, 0, 0, 0);
    __syncthreads();

    const u32 uQ = smem_u32(Qs), uK = smem_u32(Ks), uVt = smem_u32(Vts);

    for (int e = t; e < 1176; e += 384) {
        int f = e & 3, tok = (e >> 2) % 49, h = e / 196;
        cpa16(uQ + (u32)(((h * 64 + tok) * 40 + f * 8) * 2),
              base + (size_t)tok * 576 + h * 32 + f * 8);
        cpa16(uK + (u32)(((h * 56 + tok) * 40 + f * 8) * 2),
              base + (size_t)tok * 576 + 192 + h * 32 + f * 8);
    }
    CP_COMMIT();
    for (int e = t; e < 4704; e += 384) {
        int f = e & 15, tok = (e >> 4) % 49, h = e / 784;
        float2 v = __bfloat1622float2(*(const bf162*)(base + (size_t)tok * 576 + 384 + h * 32 + 2 * f));
        Vts[(h * 32 + 2 * f) * 72 + tok]     = __float2half(v.x);
        Vts[(h * 32 + 2 * f + 1) * 72 + tok] = __float2half(v.y);
    }
    CP_WAIT0();
    __syncthreads();

    const int lane = t & 31, w = t >> 5;
    const int h = w >> 1;
    const int mbase = (w & 1) * 32;
    const int g = lane >> 2, tg = lane & 3;
    const int rb = ((lane >> 4) << 3) + (lane & 7);
    const int kbo = ((lane >> 3) & 1) * 8;

    float S[2][7][4] = {};
    const u32 aQ = uQ + (u32)(((h * 64 + mbase + (lane & 15)) * 40 + (lane >> 4) * 8) * 2);
    const u32 bK = uK + (u32)(((h * 56 + rb) * 40 + kbo) * 2);
#pragma unroll
    for (int ks = 0; ks < 2; ks++) {
        const u32 ko = (u32)(ks * 32);
        u32 a[2][4], b[14];
        ldsm_x4(a[0], aQ + ko);
        ldsm_x4(a[1], aQ + (u32)(16 * 40 * 2) + ko);
        ldsm_x4(b,      bK + ko);
        ldsm_x4(b + 4,  bK + (u32)(16 * 40 * 2) + ko);
        ldsm_x4(b + 8,  bK + (u32)(32 * 40 * 2) + ko);
        ldsm_x2(b + 12, bK + (u32)(48 * 40 * 2) + ko);
#pragma unroll
        for (int i = 0; i < 2; i++)
#pragma unroll
            for (int j = 0; j < 7; j++)
                mma16(S[i][j], a[i], b + 2 * j);
    }

    const float scale = 0.17677669529663687f;
    float rinv[2][2];
#pragma unroll
    for (int i = 0; i < 2; i++) {
        float rs0 = 0.f, rs1 = 0.f;
#pragma unroll
        for (int j = 0; j < 7; j++) {
            int n = 8 * j + 2 * tg;
            int m0r = mbase + 16 * i + g;
            float2 t0 = __ldg((const float2*)(Tb + (h * 64 + m0r) * 56 + n));
            float2 t1 = __ldg((const float2*)(Tb + (h * 64 + m0r + 8) * 56 + n));
            float e0 = __expf(fmaf(S[i][j][0], scale, t0.x));
            float e1 = __expf(fmaf(S[i][j][1], scale, t0.y));
            float e2 = __expf(fmaf(S[i][j][2], scale, t1.x));
            float e3 = __expf(fmaf(S[i][j][3], scale, t1.y));
            S[i][j][0] = e0; S[i][j][1] = e1; S[i][j][2] = e2; S[i][j][3] = e3;
            rs0 += e0 + e1; rs1 += e2 + e3;
        }
        rs0 += __shfl_xor_sync(0xffffffffu, rs0, 1);
        rs0 += __shfl_xor_sync(0xffffffffu, rs0, 2);
        rs1 += __shfl_xor_sync(0xffffffffu, rs1, 1);
        rs1 += __shfl_xor_sync(0xffffffffu, rs1, 2);
        rinv[i][0] = 1.f / rs0;
        rinv[i][1] = 1.f / rs1;
    }

    float O[2][4][4] = {};
    const u32 bV = uVt + (u32)(((h * 32 + rb) * 72 + kbo) * 2);
#pragma unroll
    for (int kk = 0; kk < 4; kk++) {
        u32 a[2][4], b[8];
#pragma unroll
        for (int i = 0; i < 2; i++) {
            int j0 = 2 * kk, j1 = 2 * kk + 1;
            half2 h0 = __floats2half2_rn(S[i][j0][0], S[i][j0][1]);
            half2 h1 = __floats2half2_rn(S[i][j0][2], S[i][j0][3]);
            a[i][0] = *(const u32*)&h0;
            a[i][1] = *(const u32*)&h1;
            if (j1 < 7) {
                half2 h2 = __floats2half2_rn(S[i][j1][0], S[i][j1][1]);
                half2 h3 = __floats2half2_rn(S[i][j1][2], S[i][j1][3]);
                a[i][2] = *(const u32*)&h2;
                a[i][3] = *(const u32*)&h3;
            } else {
                a[i][2] = 0u; a[i][3] = 0u;
            }
        }
        const u32 ko = (u32)(kk * 32);
        ldsm_x4(b,     bV + ko);
        ldsm_x4(b + 4, bV + (u32)(16 * 72 * 2) + ko);
#pragma unroll
        for (int i = 0; i < 2; i++)
#pragma unroll
            for (int j = 0; j < 4; j++)
                mma16h(O[i][j], a[i], b + 2 * j);
    }

    bf16* dst0 = g_att + (size_t)bw * NTOK * DIM + h * 32;
#pragma unroll
    for (int i = 0; i < 2; i++)
#pragma unroll
        for (int half = 0; half < 2; half++) {
            int m = mbase + 16 * i + g + 8 * half;
            if (m < NTOK) {
                float inv = rinv[i][half];
                bf16* dp = dst0 + (size_t)m * DIM + 2 * tg;
#pragma unroll
                for (int j = 0; j < 4; j++) {
                    bf162 bb = __float22bfloat162_rn(
                        make_float2(O[i][j][2 * half] * inv, O[i][j][2 * half + 1] * inv));
                    *(bf162*)(dp + 8 * j) = bb;
                }
            }
        }
}

// ---------------- launcher ----------------
extern "C" void kernel_launch(void* const* d_in, const int* in_sizes, int n_in,
                              void* d_out, int out_size) {
    int base = (n_in >= 16) ? 3 : 1;
    const float* x      = (const float*)d_in[0];
    const float* qkv_w  = (const float*)d_in[base + 0];
    const float* qkv_b  = (const float*)d_in[base + 1];
    const float* proj_w = (const float*)d_in[base + 2];
    const float* proj_b = (const float*)d_in[base + 3];
    const float* rpb    = (const float*)d_in[base + 4];
    const float* n1w    = (const float*)d_in[base + 5];
    const float* n1b    = (const float*)d_in[base + 6];
    const float* n2w    = (const float*)d_in[base + 7];
    const float* n2b    = (const float*)d_in[base + 8];
    const float* w1     = (const float*)d_in[base + 9];
    const float* b1     = (const float*)d_in[base + 10];
    const float* w2     = (const float*)d_in[base + 11];
    const float* b2     = (const float*)d_in[base + 12];
    float* out = (float*)d_out;

    cudaFuncSetAttribute(k_mma, cudaFuncAttributeMaxDynamicSharedMemorySize, MMA_SMEM);
    cudaFuncSetAttribute(k_proj, cudaFuncAttributeMaxDynamicSharedMemorySize, PRJ_SMEM);
    cudaFuncSetAttribute(k_mlp, cudaFuncAttributeMaxDynamicSharedMemorySize, MLP_SMEM);
    cudaFuncSetAttribute(k_attn, cudaFuncAttributeMaxDynamicSharedMemorySize, ATT_SMEM);

    bf16* g_wt_p;
    cudaGetSymbolAddress((void**)&g_wt_p, g_wt);

    const int nblk_ln = MTOK / 8;
    const int mt = MTOK / 128;         // 3136
    const int mt64 = MTOK / 64;        // 6272

    // 0. weight transposes + bias/mask tables
    k_trall<<<1728, 256>>>(qkv_w, proj_w, w1, w2, g_wt_p);
    k_bias<<<(4 * 6 * 64 * 56 + 255) / 256, 256>>>(rpb);
    // 1. LN1 + shifted-window gather -> g_h (bf16)
    k_ln<<<nblk_ln, 256>>>(x, n1w, n1b);
    // 2. QKV GEMM -> g_qkv (bf16), 12-warp CTAs
    k_mma<<<dim3(6, mt), 384, MMA_SMEM>>>(g_wt_p + WT_QKV, qkv_b);
    // 3. tensor-core window attention -> g_att (bf16)
    k_attn<<<NWTOT, 384, ATT_SMEM>>>();
    // 4. fused proj + residual + LN2 -> g_y (fp32), g_h (bf16 LN2 out)
    k_proj<<<mt64, 256, PRJ_SMEM>>>(g_wt_p + WT_PRJ, proj_b, x, n2w, n2b);
    // 5+6. fused MLP + residual -> d_out
    k_mlp<<<mt, 512, MLP_SMEM>>>(g_wt_p + WT_M1, g_wt_p + WT_M2, b1, b2, out);
}

// round 14
// speedup vs baseline: 1.0115x; 1.0115x over previous
#include <cuda_runtime.h>
#include <cuda_bf16.h>
#include <cuda_fp16.h>
#include <stdint.h>
#include <math.h>

using u32 = unsigned int;
using u64 = unsigned long long;
using bf16 = __nv_bfloat16;
using bf162 = __nv_bfloat162;

// ---------------- problem constants ----------------
constexpr int BATCH = 8;
constexpr int HWP   = 224;
constexpr int LPIX  = HWP * HWP;      // 50176
constexpr int DIM   = 192;
constexpr int NH    = 6;
constexpr int HD    = 32;
constexpr int DFF   = 768;
constexpr int WSZ   = 7;
constexpr int SHF   = 3;
constexpr int NTOK  = 49;
constexpr int NWTOT = 8192;
constexpr int MTOK  = BATCH * LPIX;   // 401408

// ---------------- scratch globals ----------------
__device__ bf16  g_qkv[(size_t)MTOK * 3 * DIM];
__device__ bf16  g_att[(size_t)MTOK * DIM];
__device__ float g_y  [(size_t)MTOK * DIM];       // residual stream (fp32)
__device__ bf16  g_wt [442368];                   // transposed bf16 weights
__device__ float4 g_bias4[21504];                 // bias+mask, fragment layout

constexpr int WT_QKV = 0;        // [576][192]
constexpr int WT_PRJ = 110592;   // [192][192]
constexpr int WT_M1  = 147456;   // [768][192]
constexpr int WT_M2  = 294912;   // [192][768]

// g_h: LN1 output, then (after QKV consumed it) LN2 output (bf16 [MTOK][192])
__device__ bf16  g_h  [(size_t)MTOK * DIM];

// ---------------- PTX helpers ----------------
__device__ __forceinline__ void mma16(float* c, const u32* a, const u32* b) {
    asm volatile(
        "mma.sync.aligned.m16n8k16.row.col.f32.bf16.bf16.f32 "
        "{%0,%1,%2,%3}, {%4,%5,%6,%7}, {%8,%9}, {%0,%1,%2,%3};"
        : "+f"(c[0]), "+f"(c[1]), "+f"(c[2]), "+f"(c[3])
        : "r"(a[0]), "r"(a[1]), "r"(a[2]), "r"(a[3]), "r"(b[0]), "r"(b[1]));
}
__device__ __forceinline__ void mma16h(float* c, const u32* a, const u32* b) {
    asm volatile(
        "mma.sync.aligned.m16n8k16.row.col.f32.f16.f16.f32 "
        "{%0,%1,%2,%3}, {%4,%5,%6,%7}, {%8,%9}, {%0,%1,%2,%3};"
        : "+f"(c[0]), "+f"(c[1]), "+f"(c[2]), "+f"(c[3])
        : "r"(a[0]), "r"(a[1]), "r"(a[2]), "r"(a[3]), "r"(b[0]), "r"(b[1]));
}
__device__ __forceinline__ void ldsm_x4(u32* r, u32 addr) {
    asm volatile("ldmatrix.sync.aligned.m8n8.x4.shared.b16 {%0,%1,%2,%3}, [%4];"
        : "=r"(r[0]), "=r"(r[1]), "=r"(r[2]), "=r"(r[3]) : "r"(addr));
}
__device__ __forceinline__ void ldsm_x2(u32* r, u32 addr) {
    asm volatile("ldmatrix.sync.aligned.m8n8.x2.shared.b16 {%0,%1}, [%2];"
        : "=r"(r[0]), "=r"(r[1]) : "r"(addr));
}
__device__ __forceinline__ u32 smem_u32(const void* p) {
    u32 a; asm("{ .reg .u64 t; cvta.to.shared.u64 t, %1; cvt.u32.u64 %0, t; }" : "=r"(a) : "l"(p));
    return a;
}
__device__ __forceinline__ void cpa16(u32 saddr, const void* gaddr) {
    asm volatile("cp.async.cg.shared.global [%0], [%1], 16;" :: "r"(saddr), "l"(gaddr));
}
#define CP_COMMIT() asm volatile("cp.async.commit_group;" ::: "memory")
#define CP_WAIT2()  asm volatile("cp.async.wait_group 2;" ::: "memory")
#define CP_WAIT1()  asm volatile("cp.async.wait_group 1;" ::: "memory")
#define CP_WAIT0()  asm volatile("cp.async.wait_group 0;" ::: "memory")

// fast gelu: tanh form
__device__ __forceinline__ float gelu_f(float v) {
    float u = v * (0.7978845608028654f + 0.035677408136300125f * v * v);
    float th; asm("tanh.approx.f32 %0, %1;" : "=f"(th) : "f"(u));
    return 0.5f * v * (1.f + th);
}

// reverse window-partition + roll(+3)
__device__ __forceinline__ size_t scat_row(int m) {
    int bw = m / NTOK, n = m - bw * NTOK;
    int bb = bw >> 10, wdx = bw & 1023;
    int wi = wdx >> 5, wj = wdx & 31;
    int r = n / WSZ, cc = n - r * WSZ;
    int pi = wi * WSZ + r + SHF; if (pi >= HWP) pi -= HWP;
    int pj = wj * WSZ + cc + SHF; if (pj >= HWP) pj -= HWP;
    return ((size_t)bb * LPIX + (size_t)pi * HWP + pj) * DIM;
}

// ---------------- all weight transposes in one launch --------------------
__global__ void k_trall(const float* __restrict__ qkv_w, const float* __restrict__ proj_w,
                        const float* __restrict__ w1, const float* __restrict__ w2,
                        bf16* __restrict__ wt) {
    int i = blockIdx.x * 256 + threadIdx.x;
    if (i < 110592) {
        int k = i / 576, n = i - k * 576;
        wt[WT_QKV + n * 192 + k] = __float2bfloat16(qkv_w[i]);
    } else if (i < 147456) {
        int j = i - 110592; int k = j / 192, n = j - k * 192;
        wt[WT_PRJ + n * 192 + k] = __float2bfloat16(proj_w[j]);
    } else if (i < 294912) {
        int j = i - 147456; int k = j / 768, n = j - k * 768;
        wt[WT_M1 + n * 192 + k] = __float2bfloat16(w1[j]);
    } else if (i < 442368) {
        int j = i - 294912; int k = j / 192, n = j - k * 192;
        wt[WT_M2 + n * 768 + k] = __float2bfloat16(w2[j]);
    }
}

// ---------------- bias+mask table in per-fragment layout ------------------
// idx = ((((tt*6 + h)*2 + wh)*2 + i)*7 + j)*32 + lane
// float4 = { T[m0][n], T[m0][n+1], T[m0+8][n], T[m0+8][n+1] }
// m0 = wh*32 + i*16 + (lane>>2); n = 8*j + 2*(lane&3); pads -> -1e30.
__global__ void k_bias4(const float* __restrict__ rpb) {
    int idx = blockIdx.x * 256 + threadIdx.x;
    if (idx >= 21504) return;
    int lane = idx & 31;
    int j  = (idx >> 5) % 7;
    int i  = (idx / 224) % 2;
    int wh = (idx / 448) % 2;
    int h  = (idx / 896) % 6;
    int tt = idx / 5376;
    int m0 = wh * 32 + i * 16 + (lane >> 2);
    int n0 = 8 * j + 2 * (lane & 3);
    int bi = tt >> 1, bj = tt & 1;
    float v[4];
#pragma unroll
    for (int q = 0; q < 4; q++) {
        int m = m0 + (q >> 1) * 8;
        int n = n0 + (q & 1);
        if (m >= NTOK || n >= NTOK) { v[q] = -1e30f; continue; }
        int rm = m / WSZ, cm = m % WSZ, rn = n / WSZ, cn = n % WSZ;
        float b = rpb[((rm - rn + 6) * 13 + (cm - cn + 6)) * NH + h];
        int hrm = bi ? (rm < 4 ? 1 : 2) : 0;
        int hrn = bi ? (rn < 4 ? 1 : 2) : 0;
        int gcm = bj ? (cm < 4 ? 1 : 2) : 0;
        int gcn = bj ? (cn < 4 ? 1 : 2) : 0;
        if (hrm != hrn || gcm != gcn) b -= 100.f;
        v[q] = b;
    }
    g_bias4[idx] = make_float4(v[0], v[1], v[2], v[3]);
}

// ---------------- LayerNorm1 (one warp / token), bf16 outputs ----------
__global__ void __launch_bounds__(256) k_ln(const float* __restrict__ xin,
                                            const float* __restrict__ w,
                                            const float* __restrict__ b) {
    int warp = threadIdx.x >> 5, lane = threadIdx.x & 31;
    int m = blockIdx.x * 8 + warp;
    int bw = m / NTOK, n = m - bw * NTOK;
    int bb = bw >> 10, wdx = bw & 1023;
    int wi = wdx >> 5, wj = wdx & 31;
    int r = n / WSZ, c = n - r * WSZ;
    int pi = wi * WSZ + r + SHF; if (pi >= HWP) pi -= HWP;
    int pj = wj * WSZ + c + SHF; if (pj >= HWP) pj -= HWP;
    const float* src = xin + ((size_t)bb * LPIX + (size_t)pi * HWP + pj) * DIM;
    bf16* dst = g_h + (size_t)m * DIM;

    float v[6]; float s = 0.f, s2 = 0.f;
#pragma unroll
    for (int j = 0; j < 6; j++) {
        v[j] = src[lane + 32 * j];
        s += v[j]; s2 += v[j] * v[j];
    }
#pragma unroll
    for (int o = 16; o > 0; o >>= 1) {
        s  += __shfl_xor_sync(0xffffffffu, s,  o);
        s2 += __shfl_xor_sync(0xffffffffu, s2, o);
    }
    float mu  = s * (1.f / DIM);
    float var = s2 * (1.f / DIM) - mu * mu;
    float rs  = rsqrtf(var + 1e-5f);
#pragma unroll
    for (int j = 0; j < 6; j++) {
        int kk = lane + 32 * j;
        dst[kk] = __float2bfloat16((v[j] - mu) * rs * __ldg(&w[kk]) + __ldg(&b[kk]));
    }
}

// ---------------- QKV GEMM (reverted 8-warp version) ---------------------
constexpr int PITCH2 = 200;
constexpr int MMA_SMEM = (128 + 96) * PITCH2 * 2;   // 89,600 B

__global__ void __launch_bounds__(256, 2) k_mma(const bf16* __restrict__ WT,
                                                const float* __restrict__ bias) {
    extern __shared__ bf16 smb[];
    bf16* As = smb;                      // [128][200]
    bf16* Bs = smb + 128 * PITCH2;       // [96][200]

    const int t = threadIdx.x;
    const int n0 = blockIdx.x * 96;
    const int m0 = blockIdx.y * 128;
    const bf16* A = g_h;

    const int lane = t & 31, w = t >> 5;
    const int mw = (w >> 2) * 64;
    const int nw = (w & 3) * 24;
    const int g = lane >> 2, tg = lane & 3;

    const u32 uA = smem_u32(As), uB = smem_u32(Bs);
    const u32 aq  = uA + (u32)(((mw + (lane & 15)) * PITCH2 + (lane >> 4) * 8) * 2);
    const int rb  = ((lane >> 4) << 3) + (lane & 7);
    const int kbo = ((lane >> 3) & 1) * 8;
    const u32 bq4 = uB + (u32)(((nw + rb) * PITCH2 + kbo) * 2);
    const u32 bq2 = uB + (u32)(((nw + 16 + rb) * PITCH2 + kbo) * 2);

    float acc[4][3][4] = {};

    auto stage = [&](int s) {
        const int col = (s % 3) * 64;
#pragma unroll
        for (int it = 0; it < 7; it++) {
            int id = t + it * 256;
            if (id < 1024) {
                int row = id >> 3, f = id & 7;
                cpa16(uA + (u32)((row * PITCH2 + col + f * 8) * 2),
                      A + (size_t)(m0 + row) * 192 + s * 64 + f * 8);
            } else {
                int id2 = id - 1024;
                int row = id2 >> 3, f = id2 & 7;
                cpa16(uB + (u32)((row * PITCH2 + col + f * 8) * 2),
                      WT + (size_t)(n0 + row) * 192 + s * 64 + f * 8);
            }
        }
        CP_COMMIT();
    };

    stage(0); stage(1); stage(2);

#pragma unroll 1
    for (int s = 0; s < 3; s++) {
        int rem = 2 - s;
        if (rem >= 2) { CP_WAIT2(); } else if (rem == 1) { CP_WAIT1(); } else { CP_WAIT0(); }
        __syncthreads();
        const int koff = (s % 3) * 64;
#pragma unroll
        for (int ks = 0; ks < 4; ks++) {
            const u32 kb2 = (u32)((koff + ks * 16) * 2);
            u32 a[4][4], b[6];
#pragma unroll
            for (int i = 0; i < 4; i++)
                ldsm_x4(a[i], aq + (u32)(i * 16 * PITCH2 * 2) + kb2);
            ldsm_x4(b, bq4 + kb2);
            ldsm_x2(b + 4, bq2 + kb2);
#pragma unroll
            for (int i = 0; i < 4; i++) {
                mma16(acc[i][0], a[i], b);
                mma16(acc[i][1], a[i], b + 2);
                mma16(acc[i][2], a[i], b + 4);
            }
        }
        __syncthreads();
    }

#pragma unroll
    for (int i = 0; i < 4; i++) {
        int r0 = m0 + mw + i * 16 + g;
#pragma unroll
        for (int half = 0; half < 2; half++) {
            int m = r0 + half * 8;
#pragma unroll
            for (int j = 0; j < 3; j++) {
                int col = n0 + nw + j * 8 + 2 * tg;
                float v0 = acc[i][j][half * 2 + 0] + __ldg(&bias[col]);
                float v1 = acc[i][j][half * 2 + 1] + __ldg(&bias[col + 1]);
                *(bf162*)(g_qkv + (size_t)m * 576 + col) =
                    __float22bfloat162_rn(make_float2(v0, v1));
            }
        }
    }
}

// ---------------- fused proj + residual + LN2 ----------------------------
constexpr int PRJ_SMEM = (64 + 192) * PITCH2 * 2;   // 102,400 B

__global__ void __launch_bounds__(256, 2) k_proj(const bf16* __restrict__ WT,
                                                 const float* __restrict__ bias,
                                                 const float* __restrict__ x,
                                                 const float* __restrict__ n2w,
                                                 const float* __restrict__ n2b) {
    extern __shared__ bf16 smb[];
    bf16* As = smb;                      // [64][200]
    bf16* Bs = smb + 64 * PITCH2;        // [192][200]

    const int t = threadIdx.x;
    const int m0 = blockIdx.x * 64;

    const int lane = t & 31, w = t >> 5;
    const int nw = w * 24;               // 8 warps x 24 = 192
    const int g = lane >> 2, tg = lane & 3;

    const u32 uA = smem_u32(As), uB = smem_u32(Bs);
    const u32 aq  = uA + (u32)(((lane & 15) * PITCH2 + (lane >> 4) * 8) * 2);
    const int rb  = ((lane >> 4) << 3) + (lane & 7);
    const int kbo = ((lane >> 3) & 1) * 8;
    const u32 bq4 = uB + (u32)(((nw + rb) * PITCH2 + kbo) * 2);
    const u32 bq2 = uB + (u32)(((nw + 16 + rb) * PITCH2 + kbo) * 2);

    float acc[4][3][4] = {};

    auto stage = [&](int s) {
        const int col = (s % 3) * 64;
#pragma unroll
        for (int it = 0; it < 8; it++) {
            int id = t + it * 256;
            if (id < 512) {
                int row = id >> 3, f = id & 7;
                cpa16(uA + (u32)((row * PITCH2 + col + f * 8) * 2),
                      g_att + (size_t)(m0 + row) * 192 + s * 64 + f * 8);
            } else {
                int id2 = id - 512;
                int row = id2 >> 3, f = id2 & 7;
                cpa16(uB + (u32)((row * PITCH2 + col + f * 8) * 2),
                      WT + (size_t)row * 192 + s * 64 + f * 8);
            }
        }
        CP_COMMIT();
    };

    stage(0); stage(1); stage(2);

#pragma unroll 1
    for (int s = 0; s < 3; s++) {
        int rem = 2 - s;
        if (rem >= 2) { CP_WAIT2(); } else if (rem == 1) { CP_WAIT1(); } else { CP_WAIT0(); }
        __syncthreads();
        const int koff = (s % 3) * 64;
#pragma unroll
        for (int ks = 0; ks < 4; ks++) {
            const u32 kb2 = (u32)((koff + ks * 16) * 2);
            u32 a[4][4], b[6];
#pragma unroll
            for (int i = 0; i < 4; i++)
                ldsm_x4(a[i], aq + (u32)(i * 16 * PITCH2 * 2) + kb2);
            ldsm_x4(b, bq4 + kb2);
            ldsm_x2(b + 4, bq2 + kb2);
#pragma unroll
            for (int i = 0; i < 4; i++) {
                mma16(acc[i][0], a[i], b);
                mma16(acc[i][1], a[i], b + 2);
                mma16(acc[i][2], a[i], b + 4);
            }
        }
        __syncthreads();
    }

    // ---- epilogue: y = acc + bias + x; row reduce; LN; dual store ----
    float* red = (float*)smb;            // [64][8 warps][2] = 4KB
    float* murs = red + 1024;            // [64][2]

#pragma unroll
    for (int i = 0; i < 4; i++) {
#pragma unroll
        for (int half = 0; half < 2; half++) {
            int row = i * 16 + g + 8 * half;
            size_t srow = scat_row(m0 + row);
            float s = 0.f, s2 = 0.f;
#pragma unroll
            for (int j = 0; j < 3; j++) {
                int col = nw + j * 8 + 2 * tg;
                float2 xr = *(const float2*)(x + srow + col);
                float v0 = acc[i][j][half * 2 + 0] + __ldg(&bias[col]) + xr.x;
                float v1 = acc[i][j][half * 2 + 1] + __ldg(&bias[col + 1]) + xr.y;
                acc[i][j][half * 2 + 0] = v0;
                acc[i][j][half * 2 + 1] = v1;
                s += v0 + v1; s2 += v0 * v0 + v1 * v1;
            }
            s  += __shfl_xor_sync(0xffffffffu, s, 1);
            s  += __shfl_xor_sync(0xffffffffu, s, 2);
            s2 += __shfl_xor_sync(0xffffffffu, s2, 1);
            s2 += __shfl_xor_sync(0xffffffffu, s2, 2);
            if (tg == 0) {
                red[row * 16 + w * 2 + 0] = s;
                red[row * 16 + w * 2 + 1] = s2;
            }
        }
    }
    __syncthreads();
    if (t < 64) {
        float s = 0.f, s2 = 0.f;
#pragma unroll
        for (int w8 = 0; w8 < 8; w8++) {
            s  += red[t * 16 + w8 * 2 + 0];
            s2 += red[t * 16 + w8 * 2 + 1];
        }
        float mu = s * (1.f / DIM);
        float var = s2 * (1.f / DIM) - mu * mu;
        murs[t * 2 + 0] = mu;
        murs[t * 2 + 1] = rsqrtf(var + 1e-5f);
    }
    __syncthreads();

#pragma unroll
    for (int i = 0; i < 4; i++) {
#pragma unroll
        for (int half = 0; half < 2; half++) {
            int row = i * 16 + g + 8 * half;
            size_t srow = scat_row(m0 + row);
            float mu = murs[row * 2 + 0], rs = murs[row * 2 + 1];
#pragma unroll
            for (int j = 0; j < 3; j++) {
                int col = nw + j * 8 + 2 * tg;
                float v0 = acc[i][j][half * 2 + 0];
                float v1 = acc[i][j][half * 2 + 1];
                *(float2*)(g_y + srow + col) = make_float2(v0, v1);
                float a0 = (v0 - mu) * rs * __ldg(&n2w[col]) + __ldg(&n2b[col]);
                float a1 = (v1 - mu) * rs * __ldg(&n2w[col + 1]) + __ldg(&n2b[col + 1]);
                *(bf162*)(g_h + srow + col) = __float22bfloat162_rn(make_float2(a0, a1));
            }
        }
    }
}

// ---------------- fused MLP ----------------
constexpr int MLP_SMEM = 196096;   // bytes

__global__ void __launch_bounds__(512, 1) k_mlp(const bf16* __restrict__ W1T,
                                                const bf16* __restrict__ W2T,
                                                const float* __restrict__ b1,
                                                const float* __restrict__ b2,
                                                float* __restrict__ dout) {
    extern __shared__ bf16 smb[];
    bf16* Asm = smb;                 // [128][200]
    bf16* Hs  = smb + 25600;         // [128][104]
    bf16* W1s = smb + 38912;         // [96][200]
    bf16* W2s = smb + 58112;         // [2][192][104]

    const int t = threadIdx.x;
    const int m0 = blockIdx.x * 128;
    const int lane = t & 31, w = t >> 5;
    const int mwp = (w >> 2) * 32;
    const int nwA = (w & 3) * 24;
    const int nwB = (w & 3) * 48;
    const int g = lane >> 2, tg = lane & 3;

    const u32 uA = smem_u32(Asm), uH = smem_u32(Hs);
    const u32 uW1 = smem_u32(W1s), uW2 = smem_u32(W2s);

    const u32 aqA = uA + (u32)(((mwp + (lane & 15)) * 200 + (lane >> 4) * 8) * 2);
    const u32 aqB = uH + (u32)(((mwp + (lane & 15)) * 104 + (lane >> 4) * 8) * 2);
    const int rb  = ((lane >> 4) << 3) + (lane & 7);
    const int kbo = ((lane >> 3) & 1) * 8;
    const u32 bq4A = uW1 + (u32)(((nwA + rb) * 200 + kbo) * 2);
    const u32 bq2A = uW1 + (u32)(((nwA + 16 + rb) * 200 + kbo) * 2);

    float accB[2][6][4] = {};

    auto stage_A = [&] {
        for (int id = t; id < 3072; id += 512) {
            int row = id / 24, f = id - row * 24;
            cpa16(uA + (u32)((row * 200 + f * 8) * 2),
                  g_h + (size_t)(m0 + row) * DIM + f * 8);
        }
    };
    auto stage_W1 = [&](int c) {
        for (int id = t; id < 2304; id += 512) {
            int row = id / 24, f = id - row * 24;
            cpa16(uW1 + (u32)((row * 200 + f * 8) * 2),
                  W1T + (size_t)(96 * c + row) * DIM + f * 8);
        }
    };
    auto stage_W2 = [&](int c) {
        const u32 base = uW2 + (u32)((c & 1) * 19968 * 2);
        for (int id = t; id < 2304; id += 512) {
            int row = id / 12, f = id - row * 12;
            cpa16(base + (u32)((row * 104 + f * 8) * 2),
                  W2T + (size_t)row * DFF + 96 * c + f * 8);
        }
    };

    stage_A(); stage_W1(0); stage_W2(0); CP_COMMIT();
    stage_W2(1); CP_COMMIT();

#pragma unroll 1
    for (int c = 0; c < 8; c++) {
        if (c < 7) { CP_WAIT1(); } else { CP_WAIT0(); }
        __syncthreads();

        float acc2[2][3][4] = {};
#pragma unroll
        for (int ks = 0; ks < 12; ks++) {
            const u32 kb = (u32)(ks * 32);
            u32 a[2][4], b[6];
            ldsm_x4(a[0], aqA + kb);
            ldsm_x4(a[1], aqA + (u32)(16 * 200 * 2) + kb);
            ldsm_x4(b, bq4A + kb);
            ldsm_x2(b + 4, bq2A + kb);
#pragma unroll
            for (int i = 0; i < 2; i++) {
                mma16(acc2[i][0], a[i], b);
                mma16(acc2[i][1], a[i], b + 2);
                mma16(acc2[i][2], a[i], b + 4);
            }
        }
        __syncthreads();

        if (c + 1 < 8) { stage_W1(c + 1); CP_COMMIT(); }

#pragma unroll
        for (int i = 0; i < 2; i++)
#pragma unroll
            for (int half = 0; half < 2; half++) {
                int row = mwp + i * 16 + g + half * 8;
#pragma unroll
                for (int j = 0; j < 3; j++) {
                    int col = nwA + j * 8 + 2 * tg;
                    int gcol = c * 96 + col;
                    float v0 = acc2[i][j][half * 2 + 0] + __ldg(&b1[gcol]);
                    float v1 = acc2[i][j][half * 2 + 1] + __ldg(&b1[gcol + 1]);
                    *(bf162*)(Hs + row * 104 + col) =
                        __float22bfloat162_rn(make_float2(gelu_f(v0), gelu_f(v1)));
                }
            }
        __syncthreads();
        CP_WAIT2();

        const u32 w2b = uW2 + (u32)((c & 1) * 19968 * 2);
#pragma unroll
        for (int ks = 0; ks < 6; ks++) {
            const u32 kb = (u32)(ks * 32);
            u32 a[2][4], b[12];
            ldsm_x4(a[0], aqB + kb);
            ldsm_x4(a[1], aqB + (u32)(16 * 104 * 2) + kb);
#pragma unroll
            for (int j2 = 0; j2 < 3; j2++)
                ldsm_x4(b + j2 * 4,
                        w2b + (u32)(((nwB + j2 * 16 + rb) * 104 + kbo) * 2) + kb);
#pragma unroll
            for (int i = 0; i < 2; i++)
#pragma unroll
                for (int jn = 0; jn < 6; jn++)
                    mma16(accB[i][jn], a[i], b + jn * 2);
        }
        __syncthreads();

        if (c + 2 < 8) { stage_W2(c + 2); CP_COMMIT(); }
    }

#pragma unroll
    for (int i = 0; i < 2; i++)
#pragma unroll
        for (int half = 0; half < 2; half++) {
            int m = m0 + mwp + i * 16 + g + half * 8;
#pragma unroll
            for (int jn = 0; jn < 6; jn++) {
                int col = nwB + jn * 8 + 2 * tg;
                const float* yy = g_y + (size_t)m * DIM + col;
                float v0 = accB[i][jn][half * 2 + 0] + __ldg(&b2[col]) + yy[0];
                float v1 = accB[i][jn][half * 2 + 1] + __ldg(&b2[col + 1]) + yy[1];
                *(float2*)(dout + (size_t)m * DIM + col) = make_float2(v0, v1);
            }
        }
}

// ---------------- tensor-core windowed attention -------------------------
// smem (bf16 units): Q[6][64][40] @0, K[6][56][40] @15360, Vt(half)[6][32][72] @28800
constexpr int ATT_SMEM = 85248;

__global__ void __launch_bounds__(384) k_attn() {
    extern __shared__ bf16 smb[];
    bf16*  Qs  = smb;
    bf16*  Ks  = smb + 15360;
    __half* Vts = (__half*)(smb + 28800);

    const int bw = blockIdx.x, t = threadIdx.x;
    const int wdx = bw & 1023, wi = wdx >> 5, wj = wdx & 31;
    const int tt = ((wi == 31) ? 2 : 0) + ((wj == 31) ? 1 : 0);
    const bf16* base = g_qkv + (size_t)bw * NTOK * 576;

    const u32 uQ = smem_u32(Qs), uK = smem_u32(Ks), uVt = smem_u32(Vts);

    // Q,K via cp.async
    for (int e = t; e < 1176; e += 384) {
        int f = e & 3, tok = (e >> 2) % 49, h = e / 196;
        cpa16(uQ + (u32)(((h * 64 + tok) * 40 + f * 8) * 2),
              base + (size_t)tok * 576 + h * 32 + f * 8);
        cpa16(uK + (u32)(((h * 56 + tok) * 40 + f * 8) * 2),
              base + (size_t)tok * 576 + 192 + h * 32 + f * 8);
    }
    CP_COMMIT();
    // targeted pad zeroing: K rows 49..55 (6 heads x 7 rows x 40)
    for (int e = t; e < 1680; e += 384) {
        int h = e / 280, rem = e - h * 280;
        int row = 49 + rem / 40, col = rem - (rem / 40) * 40;
        Ks[(h * 56 + row) * 40 + col] = __float2bfloat16(0.f);
    }
    // Vt pad columns 49..63 for all 192 rows
    for (int e = t; e < 192 * 15; e += 384) {
        int row = e / 15, col = 49 + e - (e / 15) * 15;
        Vts[row * 72 + col] = __float2half(0.f);
    }
    // V transposed -> fp16
    for (int e = t; e < 4704; e += 384) {
        int f = e & 15, tok = (e >> 4) % 49, h = e / 784;
        float2 v = __bfloat1622float2(*(const bf162*)(base + (size_t)tok * 576 + 384 + h * 32 + 2 * f));
        Vts[(h * 32 + 2 * f) * 72 + tok]     = __float2half(v.x);
        Vts[(h * 32 + 2 * f + 1) * 72 + tok] = __float2half(v.y);
    }
    CP_WAIT0();
    __syncthreads();

    const int lane = t & 31, w = t >> 5;
    const int h = w >> 1;
    const int mbase = (w & 1) * 32;
    const int g = lane >> 2, tg = lane & 3;
    const int rb = ((lane >> 4) << 3) + (lane & 7);
    const int kbo = ((lane >> 3) & 1) * 8;

    // ---- S = Q K^T ----
    float S[2][7][4] = {};
    const u32 aQ = uQ + (u32)(((h * 64 + mbase + (lane & 15)) * 40 + (lane >> 4) * 8) * 2);
    const u32 bK = uK + (u32)(((h * 56 + rb) * 40 + kbo) * 2);
#pragma unroll
    for (int ks = 0; ks < 2; ks++) {
        const u32 ko = (u32)(ks * 32);
        u32 a[2][4], b[14];
        ldsm_x4(a[0], aQ + ko);
        ldsm_x4(a[1], aQ + (u32)(16 * 40 * 2) + ko);
        ldsm_x4(b,      bK + ko);
        ldsm_x4(b + 4,  bK + (u32)(16 * 40 * 2) + ko);
        ldsm_x4(b + 8,  bK + (u32)(32 * 40 * 2) + ko);
        ldsm_x2(b + 12, bK + (u32)(48 * 40 * 2) + ko);
#pragma unroll
        for (int i = 0; i < 2; i++)
#pragma unroll
            for (int j = 0; j < 7; j++)
                mma16(S[i][j], a[i], b + 2 * j);
    }

    // ---- softmax (coalesced fragment-layout bias table) ----
    const float scale = 0.17677669529663687f;
    const float4* tb = g_bias4 + (((tt * 6 + h) * 2 + (w & 1)) * 2) * 224;
    float rinv[2][2];
#pragma unroll
    for (int i = 0; i < 2; i++) {
        float rs0 = 0.f, rs1 = 0.f;
#pragma unroll
        for (int j = 0; j < 7; j++) {
            float4 tv = __ldg(&tb[(i * 7 + j) * 32 + lane]);
            float e0 = __expf(fmaf(S[i][j][0], scale, tv.x));
            float e1 = __expf(fmaf(S[i][j][1], scale, tv.y));
            float e2 = __expf(fmaf(S[i][j][2], scale, tv.z));
            float e3 = __expf(fmaf(S[i][j][3], scale, tv.w));
            S[i][j][0] = e0; S[i][j][1] = e1; S[i][j][2] = e2; S[i][j][3] = e3;
            rs0 += e0 + e1; rs1 += e2 + e3;
        }
        rs0 += __shfl_xor_sync(0xffffffffu, rs0, 1);
        rs0 += __shfl_xor_sync(0xffffffffu, rs0, 2);
        rs1 += __shfl_xor_sync(0xffffffffu, rs1, 1);
        rs1 += __shfl_xor_sync(0xffffffffu, rs1, 2);
        rinv[i][0] = 1.f / rs0;
        rinv[i][1] = 1.f / rs1;
    }

    // ---- O = P V ----
    float O[2][4][4] = {};
    const u32 bV = uVt + (u32)(((h * 32 + rb) * 72 + kbo) * 2);
#pragma unroll
    for (int kk = 0; kk < 4; kk++) {
        u32 a[2][4], b[8];
#pragma unroll
        for (int i = 0; i < 2; i++) {
            int j0 = 2 * kk, j1 = 2 * kk + 1;
            half2 h0 = __floats2half2_rn(S[i][j0][0], S[i][j0][1]);
            half2 h1 = __floats2half2_rn(S[i][j0][2], S[i][j0][3]);
            a[i][0] = *(const u32*)&h0;
            a[i][1] = *(const u32*)&h1;
            if (j1 < 7) {
                half2 h2 = __floats2half2_rn(S[i][j1][0], S[i][j1][1]);
                half2 h3 = __floats2half2_rn(S[i][j1][2], S[i][j1][3]);
                a[i][2] = *(const u32*)&h2;
                a[i][3] = *(const u32*)&h3;
            } else {
                a[i][2] = 0u; a[i][3] = 0u;
            }
        }
        const u32 ko = (u32)(kk * 32);
        ldsm_x4(b,     bV + ko);
        ldsm_x4(b + 4, bV + (u32)(16 * 72 * 2) + ko);
#pragma unroll
        for (int i = 0; i < 2; i++)
#pragma unroll
            for (int j = 0; j < 4; j++)
                mma16h(O[i][j], a[i], b + 2 * j);
    }

    bf16* dst0 = g_att + (size_t)bw * NTOK * DIM + h * 32;
#pragma unroll
    for (int i = 0; i < 2; i++)
#pragma unroll
        for (int half = 0; half < 2; half++) {
            int m = mbase + 16 * i + g + 8 * half;
            if (m < NTOK) {
                float inv = rinv[i][half];
                bf16* dp = dst0 + (size_t)m * DIM + 2 * tg;
#pragma unroll
                for (int j = 0; j < 4; j++) {
                    bf162 bb = __float22bfloat162_rn(
                        make_float2(O[i][j][2 * half] * inv, O[i][j][2 * half + 1] * inv));
                    *(bf162*)(dp + 8 * j) = bb;
                }
            }
        }
}

// ---------------- launcher ----------------
extern "C" void kernel_launch(void* const* d_in, const int* in_sizes, int n_in,
                              void* d_out, int out_size) {
    int base = (n_in >= 16) ? 3 : 1;
    const float* x      = (const float*)d_in[0];
    const float* qkv_w  = (const float*)d_in[base + 0];
    const float* qkv_b  = (const float*)d_in[base + 1];
    const float* proj_w = (const float*)d_in[base + 2];
    const float* proj_b = (const float*)d_in[base + 3];
    const float* rpb    = (const float*)d_in[base + 4];
    const float* n1w    = (const float*)d_in[base + 5];
    const float* n1b    = (const float*)d_in[base + 6];
    const float* n2w    = (const float*)d_in[base + 7];
    const float* n2b    = (const float*)d_in[base + 8];
    const float* w1     = (const float*)d_in[base + 9];
    const float* b1     = (const float*)d_in[base + 10];
    const float* w2     = (const float*)d_in[base + 11];
    const float* b2     = (const float*)d_in[base + 12];
    float* out = (float*)d_out;

    cudaFuncSetAttribute(k_mma, cudaFuncAttributeMaxDynamicSharedMemorySize, MMA_SMEM);
    cudaFuncSetAttribute(k_proj, cudaFuncAttributeMaxDynamicSharedMemorySize, PRJ_SMEM);
    cudaFuncSetAttribute(k_mlp, cudaFuncAttributeMaxDynamicSharedMemorySize, MLP_SMEM);
    cudaFuncSetAttribute(k_attn, cudaFuncAttributeMaxDynamicSharedMemorySize, ATT_SMEM);

    bf16* g_wt_p;
    cudaGetSymbolAddress((void**)&g_wt_p, g_wt);

    const int nblk_ln = MTOK / 8;
    const int mt = MTOK / 128;         // 3136
    const int mt64 = MTOK / 64;        // 6272

    // 0. weight transposes + bias/mask tables
    k_trall<<<1728, 256>>>(qkv_w, proj_w, w1, w2, g_wt_p);
    k_bias4<<<(21504 + 255) / 256, 256>>>(rpb);
    // 1. LN1 + shifted-window gather -> g_h (bf16)
    k_ln<<<nblk_ln, 256>>>(x, n1w, n1b);
    // 2. QKV GEMM -> g_qkv (bf16)
    k_mma<<<dim3(6, mt), 256, MMA_SMEM>>>(g_wt_p + WT_QKV, qkv_b);
    // 3. tensor-core window attention -> g_att (bf16)
    k_attn<<<NWTOT, 384, ATT_SMEM>>>();
    // 4. fused proj + residual + LN2 -> g_y (fp32), g_h (bf16 LN2 out)
    k_proj<<<mt64, 256, PRJ_SMEM>>>(g_wt_p + WT_PRJ, proj_b, x, n2w, n2b);
    // 5+6. fused MLP + residual -> d_out
    k_mlp<<<mt, 512, MLP_SMEM>>>(g_wt_p + WT_M1, g_wt_p + WT_M2, b1, b2, out);
}

// round 15
// speedup vs baseline: 1.0231x; 1.0115x over previous
#include <cuda_runtime.h>
#include <cuda_bf16.h>
#include <cuda_fp16.h>
#include <stdint.h>
#include <math.h>

using u32 = unsigned int;
using u64 = unsigned long long;
using bf16 = __nv_bfloat16;
using bf162 = __nv_bfloat162;

// ---------------- problem constants ----------------
constexpr int BATCH = 8;
constexpr int HWP   = 224;
constexpr int LPIX  = HWP * HWP;      // 50176
constexpr int DIM   = 192;
constexpr int NH    = 6;
constexpr int HD    = 32;
constexpr int DFF   = 768;
constexpr int WSZ   = 7;
constexpr int SHF   = 3;
constexpr int NTOK  = 49;
constexpr int NWTOT = 8192;
constexpr int MTOK  = BATCH * LPIX;   // 401408

// ---------------- scratch globals ----------------
__device__ bf16  g_qkv[(size_t)MTOK * 3 * DIM];
__device__ bf16  g_att[(size_t)MTOK * DIM];
__device__ float g_y  [(size_t)MTOK * DIM];       // residual stream (fp32)
__device__ bf16  g_wt [442368];                   // transposed bf16 weights
__device__ float4 g_bias4[21504];                 // bias+mask, fragment layout

constexpr int WT_QKV = 0;        // [576][192]
constexpr int WT_PRJ = 110592;   // [192][192]
constexpr int WT_M1  = 147456;   // [768][192]
constexpr int WT_M2  = 294912;   // [192][768]

// g_h: LN1 output, then (after QKV consumed it) LN2 output (bf16 [MTOK][192])
__device__ bf16  g_h  [(size_t)MTOK * DIM];

// ---------------- PTX helpers ----------------
__device__ __forceinline__ void mma16(float* c, const u32* a, const u32* b) {
    asm volatile(
        "mma.sync.aligned.m16n8k16.row.col.f32.bf16.bf16.f32 "
        "{%0,%1,%2,%3}, {%4,%5,%6,%7}, {%8,%9}, {%0,%1,%2,%3};"
        : "+f"(c[0]), "+f"(c[1]), "+f"(c[2]), "+f"(c[3])
        : "r"(a[0]), "r"(a[1]), "r"(a[2]), "r"(a[3]), "r"(b[0]), "r"(b[1]));
}
__device__ __forceinline__ void mma16h(float* c, const u32* a, const u32* b) {
    asm volatile(
        "mma.sync.aligned.m16n8k16.row.col.f32.f16.f16.f32 "
        "{%0,%1,%2,%3}, {%4,%5,%6,%7}, {%8,%9}, {%0,%1,%2,%3};"
        : "+f"(c[0]), "+f"(c[1]), "+f"(c[2]), "+f"(c[3])
        : "r"(a[0]), "r"(a[1]), "r"(a[2]), "r"(a[3]), "r"(b[0]), "r"(b[1]));
}
__device__ __forceinline__ void ldsm_x4(u32* r, u32 addr) {
    asm volatile("ldmatrix.sync.aligned.m8n8.x4.shared.b16 {%0,%1,%2,%3}, [%4];"
        : "=r"(r[0]), "=r"(r[1]), "=r"(r[2]), "=r"(r[3]) : "r"(addr));
}
__device__ __forceinline__ void ldsm_x2(u32* r, u32 addr) {
    asm volatile("ldmatrix.sync.aligned.m8n8.x2.shared.b16 {%0,%1}, [%2];"
        : "=r"(r[0]), "=r"(r[1]) : "r"(addr));
}
__device__ __forceinline__ u32 smem_u32(const void* p) {
    u32 a; asm("{ .reg .u64 t; cvta.to.shared.u64 t, %1; cvt.u32.u64 %0, t; }" : "=r"(a) : "l"(p));
    return a;
}
__device__ __forceinline__ void cpa16(u32 saddr, const void* gaddr) {
    asm volatile("cp.async.cg.shared.global [%0], [%1], 16;" :: "r"(saddr), "l"(gaddr));
}
#define CP_COMMIT() asm volatile("cp.async.commit_group;" ::: "memory")
#define CP_WAIT2()  asm volatile("cp.async.wait_group 2;" ::: "memory")
#define CP_WAIT1()  asm volatile("cp.async.wait_group 1;" ::: "memory")
#define CP_WAIT0()  asm volatile("cp.async.wait_group 0;" ::: "memory")

// fast gelu: tanh form
__device__ __forceinline__ float gelu_f(float v) {
    float u = v * (0.7978845608028654f + 0.035677408136300125f * v * v);
    float th; asm("tanh.approx.f32 %0, %1;" : "=f"(th) : "f"(u));
    return 0.5f * v * (1.f + th);
}

// reverse window-partition + roll(+3)
__device__ __forceinline__ size_t scat_row(int m) {
    int bw = m / NTOK, n = m - bw * NTOK;
    int bb = bw >> 10, wdx = bw & 1023;
    int wi = wdx >> 5, wj = wdx & 31;
    int r = n / WSZ, cc = n - r * WSZ;
    int pi = wi * WSZ + r + SHF; if (pi >= HWP) pi -= HWP;
    int pj = wj * WSZ + cc + SHF; if (pj >= HWP) pj -= HWP;
    return ((size_t)bb * LPIX + (size_t)pi * HWP + pj) * DIM;
}

// ---------------- all weight transposes in one launch --------------------
__global__ void k_trall(const float* __restrict__ qkv_w, const float* __restrict__ proj_w,
                        const float* __restrict__ w1, const float* __restrict__ w2,
                        bf16* __restrict__ wt) {
    int i = blockIdx.x * 256 + threadIdx.x;
    if (i < 110592) {
        int k = i / 576, n = i - k * 576;
        wt[WT_QKV + n * 192 + k] = __float2bfloat16(qkv_w[i]);
    } else if (i < 147456) {
        int j = i - 110592; int k = j / 192, n = j - k * 192;
        wt[WT_PRJ + n * 192 + k] = __float2bfloat16(proj_w[j]);
    } else if (i < 294912) {
        int j = i - 147456; int k = j / 768, n = j - k * 768;
        wt[WT_M1 + n * 192 + k] = __float2bfloat16(w1[j]);
    } else if (i < 442368) {
        int j = i - 294912; int k = j / 192, n = j - k * 192;
        wt[WT_M2 + n * 768 + k] = __float2bfloat16(w2[j]);
    }
}

// ---------------- bias+mask table in per-fragment layout ------------------
__global__ void k_bias4(const float* __restrict__ rpb) {
    int idx = blockIdx.x * 256 + threadIdx.x;
    if (idx >= 21504) return;
    int lane = idx & 31;
    int j  = (idx >> 5) % 7;
    int i  = (idx / 224) % 2;
    int wh = (idx / 448) % 2;
    int h  = (idx / 896) % 6;
    int tt = idx / 5376;
    int m0 = wh * 32 + i * 16 + (lane >> 2);
    int n0 = 8 * j + 2 * (lane & 3);
    int bi = tt >> 1, bj = tt & 1;
    float v[4];
#pragma unroll
    for (int q = 0; q < 4; q++) {
        int m = m0 + (q >> 1) * 8;
        int n = n0 + (q & 1);
        if (m >= NTOK || n >= NTOK) { v[q] = -1e30f; continue; }
        int rm = m / WSZ, cm = m % WSZ, rn = n / WSZ, cn = n % WSZ;
        float b = rpb[((rm - rn + 6) * 13 + (cm - cn + 6)) * NH + h];
        int hrm = bi ? (rm < 4 ? 1 : 2) : 0;
        int hrn = bi ? (rn < 4 ? 1 : 2) : 0;
        int gcm = bj ? (cm < 4 ? 1 : 2) : 0;
        int gcn = bj ? (cn < 4 ? 1 : 2) : 0;
        if (hrm != hrn || gcm != gcn) b -= 100.f;
        v[q] = b;
    }
    g_bias4[idx] = make_float4(v[0], v[1], v[2], v[3]);
}

// ---------------- LayerNorm1 (one warp / token), bf16 outputs ----------
__global__ void __launch_bounds__(256) k_ln(const float* __restrict__ xin,
                                            const float* __restrict__ w,
                                            const float* __restrict__ b) {
    int warp = threadIdx.x >> 5, lane = threadIdx.x & 31;
    int m = blockIdx.x * 8 + warp;
    int bw = m / NTOK, n = m - bw * NTOK;
    int bb = bw >> 10, wdx = bw & 1023;
    int wi = wdx >> 5, wj = wdx & 31;
    int r = n / WSZ, c = n - r * WSZ;
    int pi = wi * WSZ + r + SHF; if (pi >= HWP) pi -= HWP;
    int pj = wj * WSZ + c + SHF; if (pj >= HWP) pj -= HWP;
    const float* src = xin + ((size_t)bb * LPIX + (size_t)pi * HWP + pj) * DIM;
    bf16* dst = g_h + (size_t)m * DIM;

    float v[6]; float s = 0.f, s2 = 0.f;
#pragma unroll
    for (int j = 0; j < 6; j++) {
        v[j] = src[lane + 32 * j];
        s += v[j]; s2 += v[j] * v[j];
    }
#pragma unroll
    for (int o = 16; o > 0; o >>= 1) {
        s  += __shfl_xor_sync(0xffffffffu, s,  o);
        s2 += __shfl_xor_sync(0xffffffffu, s2, o);
    }
    float mu  = s * (1.f / DIM);
    float var = s2 * (1.f / DIM) - mu * mu;
    float rs  = rsqrtf(var + 1e-5f);
#pragma unroll
    for (int j = 0; j < 6; j++) {
        int kk = lane + 32 * j;
        dst[kk] = __float2bfloat16((v[j] - mu) * rs * __ldg(&w[kk]) + __ldg(&b[kk]));
    }
}

// ---------------- QKV GEMM: persistent CTAs, resident B ------------------
// grid 294 = 49 m-bases x 6 n-cols. Each CTA: B[96][200] resident (staged
// once), 64 m-tiles through 3-slot A ring [128][72] spanning tile bounds.
constexpr int MMA_SMEM = (96 * 200 + 3 * 128 * 72) * 2;   // 93,696 B

__global__ void __launch_bounds__(256, 2) k_mma(const bf16* __restrict__ WT,
                                                const float* __restrict__ bias) {
    extern __shared__ bf16 smb[];
    bf16* Bs = smb;                       // [96][200] resident
    bf16* As = smb + 96 * 200;            // 3 x [128][72]

    const int t = threadIdx.x;
    const int bid = blockIdx.x;
    const int n0 = (bid % 6) * 96;
    const int m_base = bid / 6;           // 0..48
    const bf16* A = g_h;

    const int lane = t & 31, w = t >> 5;
    const int mw = (w >> 2) * 64;
    const int nw = (w & 3) * 24;
    const int g = lane >> 2, tg = lane & 3;

    const u32 uB = smem_u32(Bs), uA = smem_u32(As);
    const u32 aq  = uA + (u32)(((mw + (lane & 15)) * 72 + (lane >> 4) * 8) * 2);
    const int rb  = ((lane >> 4) << 3) + (lane & 7);
    const int kbo = ((lane >> 3) & 1) * 8;
    const u32 bq4 = uB + (u32)(((nw + rb) * 200 + kbo) * 2);
    const u32 bq2 = uB + (u32)(((nw + 16 + rb) * 200 + kbo) * 2);

    auto stage_A = [&](int q) {            // q = it*3 + s
        const int it = q / 3, s = q - it * 3;
        const int m0 = (m_base + it * 49) * 128;
        const u32 slot = uA + (u32)((q % 3) * 128 * 72 * 2);
#pragma unroll
        for (int rep = 0; rep < 4; rep++) {
            int id = t + rep * 256;        // 1024 = 128 rows x 8 f4
            int row = id >> 3, f = id & 7;
            cpa16(slot + (u32)((row * 72 + f * 8) * 2),
                  A + (size_t)(m0 + row) * 192 + s * 64 + f * 8);
        }
        CP_COMMIT();
    };

    // prologue: resident B + first A chunk in group0, then two more chunks
    for (int id = t; id < 2304; id += 256) {       // 96 rows x 24 f4
        int row = id / 24, f = id - row * 24;
        cpa16(uB + (u32)((row * 200 + f * 8) * 2),
              WT + (size_t)(n0 + row) * 192 + f * 8);
    }
    {   // A chunk 0 shares group with B
        const int m0 = m_base * 128;
        const u32 slot = uA;
#pragma unroll
        for (int rep = 0; rep < 4; rep++) {
            int id = t + rep * 256;
            int row = id >> 3, f = id & 7;
            cpa16(slot + (u32)((row * 72 + f * 8) * 2),
                  A + (size_t)(m0 + row) * 192 + f * 8);
        }
        CP_COMMIT();
    }
    stage_A(1); stage_A(2);

    float acc[4][3][4] = {};
    constexpr int TOTQ = 64 * 3;

#pragma unroll 1
    for (int q = 0; q < TOTQ; q++) {
        int rem = TOTQ - 1 - q;
        if (rem >= 2) { CP_WAIT2(); } else if (rem == 1) { CP_WAIT1(); } else { CP_WAIT0(); }
        __syncthreads();
        const int s = q % 3;
        const u32 slotoff = (u32)((q % 3) * 128 * 72 * 2);
#pragma unroll
        for (int ks = 0; ks < 4; ks++) {
            const u32 kbA = slotoff + (u32)(ks * 32);
            const u32 kbB = (u32)((s * 64 + ks * 16) * 2);
            u32 a[4][4], b[6];
#pragma unroll
            for (int i = 0; i < 4; i++)
                ldsm_x4(a[i], aq + (u32)(i * 16 * 72 * 2) + kbA);
            ldsm_x4(b, bq4 + kbB);
            ldsm_x2(b + 4, bq2 + kbB);
#pragma unroll
            for (int i = 0; i < 4; i++) {
                mma16(acc[i][0], a[i], b);
                mma16(acc[i][1], a[i], b + 2);
                mma16(acc[i][2], a[i], b + 4);
            }
        }
        __syncthreads();
        if (q + 3 < TOTQ) stage_A(q + 3);

        if (s == 2) {
            // ---- epilogue for tile it = q/3 (loads for next tile in flight)
            const int m0 = (m_base + (q / 3) * 49) * 128;
#pragma unroll
            for (int i = 0; i < 4; i++) {
                int r0 = m0 + mw + i * 16 + g;
#pragma unroll
                for (int half = 0; half < 2; half++) {
                    int m = r0 + half * 8;
#pragma unroll
                    for (int j = 0; j < 3; j++) {
                        int col = n0 + nw + j * 8 + 2 * tg;
                        float v0 = acc[i][j][half * 2 + 0] + __ldg(&bias[col]);
                        float v1 = acc[i][j][half * 2 + 1] + __ldg(&bias[col + 1]);
                        *(bf162*)(g_qkv + (size_t)m * 576 + col) =
                            __float22bfloat162_rn(make_float2(v0, v1));
                    }
                }
            }
#pragma unroll
            for (int i = 0; i < 4; i++)
#pragma unroll
                for (int j = 0; j < 3; j++)
#pragma unroll
                    for (int qq = 0; qq < 4; qq++) acc[i][j][qq] = 0.f;
        }
    }
}

// ---------------- fused proj + residual + LN2: persistent, resident B ----
// grid 296. B[192][200] resident; tiles of 64 rows via 3-slot A ring [64][72].
constexpr int PRJ_SMEM = (192 * 200 + 3 * 64 * 72) * 2;   // 104,448 B

__global__ void __launch_bounds__(256, 2) k_proj(const bf16* __restrict__ WT,
                                                 const float* __restrict__ bias,
                                                 const float* __restrict__ x,
                                                 const float* __restrict__ n2w,
                                                 const float* __restrict__ n2b) {
    extern __shared__ bf16 smb[];
    bf16* Bs = smb;                       // [192][200] resident
    bf16* As = smb + 192 * 200;           // 3 x [64][72]
    __shared__ float red[1024];           // [64][8 warps][2]
    __shared__ float murs[128];           // [64][2]

    const int t = threadIdx.x;
    const int bid = blockIdx.x;
    const int NT = (6272 - bid + 295) / 296;   // tiles for this CTA
    const int totq = NT * 3;

    const int lane = t & 31, w = t >> 5;
    const int nw = w * 24;                // 8 warps x 24 = 192
    const int g = lane >> 2, tg = lane & 3;

    const u32 uB = smem_u32(Bs), uA = smem_u32(As);
    const u32 aq  = uA + (u32)(((lane & 15) * 72 + (lane >> 4) * 8) * 2);
    const int rb  = ((lane >> 4) << 3) + (lane & 7);
    const int kbo = ((lane >> 3) & 1) * 8;
    const u32 bq4 = uB + (u32)(((nw + rb) * 200 + kbo) * 2);
    const u32 bq2 = uB + (u32)(((nw + 16 + rb) * 200 + kbo) * 2);

    auto stage_A = [&](int q) {
        const int it = q / 3, s = q - it * 3;
        const int m0 = (bid + it * 296) * 64;
        const u32 slot = uA + (u32)((q % 3) * 64 * 72 * 2);
#pragma unroll
        for (int rep = 0; rep < 2; rep++) {
            int id = t + rep * 256;        // 512 = 64 rows x 8 f4
            int row = id >> 3, f = id & 7;
            cpa16(slot + (u32)((row * 72 + f * 8) * 2),
                  g_att + (size_t)(m0 + row) * 192 + s * 64 + f * 8);
        }
        CP_COMMIT();
    };

    // prologue: resident B (192x24 f4) + A chunk 0 in group0
    for (int id = t; id < 4608; id += 256) {
        int row = id / 24, f = id - row * 24;
        cpa16(uB + (u32)((row * 200 + f * 8) * 2),
              WT + (size_t)row * 192 + f * 8);
    }
    {
        const int m0 = bid * 64;
        const u32 slot = uA;
#pragma unroll
        for (int rep = 0; rep < 2; rep++) {
            int id = t + rep * 256;
            int row = id >> 3, f = id & 7;
            cpa16(slot + (u32)((row * 72 + f * 8) * 2),
                  g_att + (size_t)(m0 + row) * 192 + f * 8);
        }
        CP_COMMIT();
    }
    if (totq > 1) stage_A(1);
    if (totq > 2) stage_A(2);

    float acc[4][3][4] = {};

#pragma unroll 1
    for (int q = 0; q < totq; q++) {
        int rem = totq - 1 - q;
        if (rem >= 2) { CP_WAIT2(); } else if (rem == 1) { CP_WAIT1(); } else { CP_WAIT0(); }
        __syncthreads();
        const int s = q % 3;
        const u32 slotoff = (u32)((q % 3) * 64 * 72 * 2);
#pragma unroll
        for (int ks = 0; ks < 4; ks++) {
            const u32 kbA = slotoff + (u32)(ks * 32);
            const u32 kbB = (u32)((s * 64 + ks * 16) * 2);
            u32 a[4][4], b[6];
#pragma unroll
            for (int i = 0; i < 4; i++)
                ldsm_x4(a[i], aq + (u32)(i * 16 * 72 * 2) + kbA);
            ldsm_x4(b, bq4 + kbB);
            ldsm_x2(b + 4, bq2 + kbB);
#pragma unroll
            for (int i = 0; i < 4; i++) {
                mma16(acc[i][0], a[i], b);
                mma16(acc[i][1], a[i], b + 2);
                mma16(acc[i][2], a[i], b + 4);
            }
        }
        __syncthreads();
        if (q + 3 < totq) stage_A(q + 3);

        if (s == 2) {
            const int m0 = (bid + (q / 3) * 296) * 64;
            // ---- epilogue: y = acc + bias + x; LN; dual store ----
#pragma unroll
            for (int i = 0; i < 4; i++) {
#pragma unroll
                for (int half = 0; half < 2; half++) {
                    int row = i * 16 + g + 8 * half;
                    size_t srow = scat_row(m0 + row);
                    float s1 = 0.f, s2v = 0.f;
#pragma unroll
                    for (int j = 0; j < 3; j++) {
                        int col = nw + j * 8 + 2 * tg;
                        float2 xr = *(const float2*)(x + srow + col);
                        float v0 = acc[i][j][half * 2 + 0] + __ldg(&bias[col]) + xr.x;
                        float v1 = acc[i][j][half * 2 + 1] + __ldg(&bias[col + 1]) + xr.y;
                        acc[i][j][half * 2 + 0] = v0;
                        acc[i][j][half * 2 + 1] = v1;
                        s1 += v0 + v1; s2v += v0 * v0 + v1 * v1;
                    }
                    s1  += __shfl_xor_sync(0xffffffffu, s1, 1);
                    s1  += __shfl_xor_sync(0xffffffffu, s1, 2);
                    s2v += __shfl_xor_sync(0xffffffffu, s2v, 1);
                    s2v += __shfl_xor_sync(0xffffffffu, s2v, 2);
                    if (tg == 0) {
                        red[row * 16 + w * 2 + 0] = s1;
                        red[row * 16 + w * 2 + 1] = s2v;
                    }
                }
            }
            __syncthreads();
            if (t < 64) {
                float s1 = 0.f, s2v = 0.f;
#pragma unroll
                for (int w8 = 0; w8 < 8; w8++) {
                    s1  += red[t * 16 + w8 * 2 + 0];
                    s2v += red[t * 16 + w8 * 2 + 1];
                }
                float mu = s1 * (1.f / DIM);
                float var = s2v * (1.f / DIM) - mu * mu;
                murs[t * 2 + 0] = mu;
                murs[t * 2 + 1] = rsqrtf(var + 1e-5f);
            }
            __syncthreads();
#pragma unroll
            for (int i = 0; i < 4; i++) {
#pragma unroll
                for (int half = 0; half < 2; half++) {
                    int row = i * 16 + g + 8 * half;
                    size_t srow = scat_row(m0 + row);
                    float mu = murs[row * 2 + 0], rs = murs[row * 2 + 1];
#pragma unroll
                    for (int j = 0; j < 3; j++) {
                        int col = nw + j * 8 + 2 * tg;
                        float v0 = acc[i][j][half * 2 + 0];
                        float v1 = acc[i][j][half * 2 + 1];
                        *(float2*)(g_y + srow + col) = make_float2(v0, v1);
                        float a0 = (v0 - mu) * rs * __ldg(&n2w[col]) + __ldg(&n2b[col]);
                        float a1 = (v1 - mu) * rs * __ldg(&n2w[col + 1]) + __ldg(&n2b[col + 1]);
                        *(bf162*)(g_h + srow + col) =
                            __float22bfloat162_rn(make_float2(a0, a1));
                    }
                }
            }
#pragma unroll
            for (int i = 0; i < 4; i++)
#pragma unroll
                for (int j = 0; j < 3; j++)
#pragma unroll
                    for (int qq = 0; qq < 4; qq++) acc[i][j][qq] = 0.f;
        }
    }
}

// ---------------- fused MLP ----------------
constexpr int MLP_SMEM = 196096;   // bytes

__global__ void __launch_bounds__(512, 1) k_mlp(const bf16* __restrict__ W1T,
                                                const bf16* __restrict__ W2T,
                                                const float* __restrict__ b1,
                                                const float* __restrict__ b2,
                                                float* __restrict__ dout) {
    extern __shared__ bf16 smb[];
    bf16* Asm = smb;                 // [128][200]
    bf16* Hs  = smb + 25600;         // [128][104]
    bf16* W1s = smb + 38912;         // [96][200]
    bf16* W2s = smb + 58112;         // [2][192][104]

    const int t = threadIdx.x;
    const int m0 = blockIdx.x * 128;
    const int lane = t & 31, w = t >> 5;
    const int mwp = (w >> 2) * 32;
    const int nwA = (w & 3) * 24;
    const int nwB = (w & 3) * 48;
    const int g = lane >> 2, tg = lane & 3;

    const u32 uA = smem_u32(Asm), uH = smem_u32(Hs);
    const u32 uW1 = smem_u32(W1s), uW2 = smem_u32(W2s);

    const u32 aqA = uA + (u32)(((mwp + (lane & 15)) * 200 + (lane >> 4) * 8) * 2);
    const u32 aqB = uH + (u32)(((mwp + (lane & 15)) * 104 + (lane >> 4) * 8) * 2);
    const int rb  = ((lane >> 4) << 3) + (lane & 7);
    const int kbo = ((lane >> 3) & 1) * 8;
    const u32 bq4A = uW1 + (u32)(((nwA + rb) * 200 + kbo) * 2);
    const u32 bq2A = uW1 + (u32)(((nwA + 16 + rb) * 200 + kbo) * 2);

    float accB[2][6][4] = {};

    auto stage_A = [&] {
        for (int id = t; id < 3072; id += 512) {
            int row = id / 24, f = id - row * 24;
            cpa16(uA + (u32)((row * 200 + f * 8) * 2),
                  g_h + (size_t)(m0 + row) * DIM + f * 8);
        }
    };
    auto stage_W1 = [&](int c) {
        for (int id = t; id < 2304; id += 512) {
            int row = id / 24, f = id - row * 24;
            cpa16(uW1 + (u32)((row * 200 + f * 8) * 2),
                  W1T + (size_t)(96 * c + row) * DIM + f * 8);
        }
    };
    auto stage_W2 = [&](int c) {
        const u32 base = uW2 + (u32)((c & 1) * 19968 * 2);
        for (int id = t; id < 2304; id += 512) {
            int row = id / 12, f = id - row * 12;
            cpa16(base + (u32)((row * 104 + f * 8) * 2),
                  W2T + (size_t)row * DFF + 96 * c + f * 8);
        }
    };

    stage_A(); stage_W1(0); stage_W2(0); CP_COMMIT();
    stage_W2(1); CP_COMMIT();

#pragma unroll 1
    for (int c = 0; c < 8; c++) {
        if (c < 7) { CP_WAIT1(); } else { CP_WAIT0(); }
        __syncthreads();

        float acc2[2][3][4] = {};
#pragma unroll
        for (int ks = 0; ks < 12; ks++) {
            const u32 kb = (u32)(ks * 32);
            u32 a[2][4], b[6];
            ldsm_x4(a[0], aqA + kb);
            ldsm_x4(a[1], aqA + (u32)(16 * 200 * 2) + kb);
            ldsm_x4(b, bq4A + kb);
            ldsm_x2(b + 4, bq2A + kb);
#pragma unroll
            for (int i = 0; i < 2; i++) {
                mma16(acc2[i][0], a[i], b);
                mma16(acc2[i][1], a[i], b + 2);
                mma16(acc2[i][2], a[i], b + 4);
            }
        }
        __syncthreads();

        if (c + 1 < 8) { stage_W1(c + 1); CP_COMMIT(); }

#pragma unroll
        for (int i = 0; i < 2; i++)
#pragma unroll
            for (int half = 0; half < 2; half++) {
                int row = mwp + i * 16 + g + half * 8;
#pragma unroll
                for (int j = 0; j < 3; j++) {
                    int col = nwA + j * 8 + 2 * tg;
                    int gcol = c * 96 + col;
                    float v0 = acc2[i][j][half * 2 + 0] + __ldg(&b1[gcol]);
                    float v1 = acc2[i][j][half * 2 + 1] + __ldg(&b1[gcol + 1]);
                    *(bf162*)(Hs + row * 104 + col) =
                        __float22bfloat162_rn(make_float2(gelu_f(v0), gelu_f(v1)));
                }
            }
        __syncthreads();
        CP_WAIT2();

        const u32 w2b = uW2 + (u32)((c & 1) * 19968 * 2);
#pragma unroll
        for (int ks = 0; ks < 6; ks++) {
            const u32 kb = (u32)(ks * 32);
            u32 a[2][4], b[12];
            ldsm_x4(a[0], aqB + kb);
            ldsm_x4(a[1], aqB + (u32)(16 * 104 * 2) + kb);
#pragma unroll
            for (int j2 = 0; j2 < 3; j2++)
                ldsm_x4(b + j2 * 4,
                        w2b + (u32)(((nwB + j2 * 16 + rb) * 104 + kbo) * 2) + kb);
#pragma unroll
            for (int i = 0; i < 2; i++)
#pragma unroll
                for (int jn = 0; jn < 6; jn++)
                    mma16(accB[i][jn], a[i], b + jn * 2);
        }
        __syncthreads();

        if (c + 2 < 8) { stage_W2(c + 2); CP_COMMIT(); }
    }

#pragma unroll
    for (int i = 0; i < 2; i++)
#pragma unroll
        for (int half = 0; half < 2; half++) {
            int m = m0 + mwp + i * 16 + g + half * 8;
#pragma unroll
            for (int jn = 0; jn < 6; jn++) {
                int col = nwB + jn * 8 + 2 * tg;
                const float* yy = g_y + (size_t)m * DIM + col;
                float v0 = accB[i][jn][half * 2 + 0] + __ldg(&b2[col]) + yy[0];
                float v1 = accB[i][jn][half * 2 + 1] + __ldg(&b2[col + 1]) + yy[1];
                *(float2*)(dout + (size_t)m * DIM + col) = make_float2(v0, v1);
            }
        }
}

// ---------------- tensor-core windowed attention -------------------------
constexpr int ATT_SMEM = 85248;

__global__ void __launch_bounds__(384) k_attn() {
    extern __shared__ bf16 smb[];
    bf16*  Qs  = smb;
    bf16*  Ks  = smb + 15360;
    __half* Vts = (__half*)(smb + 28800);

    const int bw = blockIdx.x, t = threadIdx.x;
    const int wdx = bw & 1023, wi = wdx >> 5, wj = wdx & 31;
    const int tt = ((wi == 31) ? 2 : 0) + ((wj == 31) ? 1 : 0);
    const bf16* base = g_qkv + (size_t)bw * NTOK * 576;

    const u32 uQ = smem_u32(Qs), uK = smem_u32(Ks), uVt = smem_u32(Vts);

    for (int e = t; e < 1176; e += 384) {
        int f = e & 3, tok = (e >> 2) % 49, h = e / 196;
        cpa16(uQ + (u32)(((h * 64 + tok) * 40 + f * 8) * 2),
              base + (size_t)tok * 576 + h * 32 + f * 8);
        cpa16(uK + (u32)(((h * 56 + tok) * 40 + f * 8) * 2),
              base + (size_t)tok * 576 + 192 + h * 32 + f * 8);
    }
    CP_COMMIT();
    for (int e = t; e < 1680; e += 384) {
        int h = e / 280, rem = e - h * 280;
        int row = 49 + rem / 40, col = rem - (rem / 40) * 40;
        Ks[(h * 56 + row) * 40 + col] = __float2bfloat16(0.f);
    }
    for (int e = t; e < 192 * 15; e += 384) {
        int row = e / 15, col = 49 + e - (e / 15) * 15;
        Vts[row * 72 + col] = __float2half(0.f);
    }
    for (int e = t; e < 4704; e += 384) {
        int f = e & 15, tok = (e >> 4) % 49, h = e / 784;
        float2 v = __bfloat1622float2(*(const bf162*)(base + (size_t)tok * 576 + 384 + h * 32 + 2 * f));
        Vts[(h * 32 + 2 * f) * 72 + tok]     = __float2half(v.x);
        Vts[(h * 32 + 2 * f + 1) * 72 + tok] = __float2half(v.y);
    }
    CP_WAIT0();
    __syncthreads();

    const int lane = t & 31, w = t >> 5;
    const int h = w >> 1;
    const int mbase = (w & 1) * 32;
    const int g = lane >> 2, tg = lane & 3;
    const int rb = ((lane >> 4) << 3) + (lane & 7);
    const int kbo = ((lane >> 3) & 1) * 8;

    float S[2][7][4] = {};
    const u32 aQ = uQ + (u32)(((h * 64 + mbase + (lane & 15)) * 40 + (lane >> 4) * 8) * 2);
    const u32 bK = uK + (u32)(((h * 56 + rb) * 40 + kbo) * 2);
#pragma unroll
    for (int ks = 0; ks < 2; ks++) {
        const u32 ko = (u32)(ks * 32);
        u32 a[2][4], b[14];
        ldsm_x4(a[0], aQ + ko);
        ldsm_x4(a[1], aQ + (u32)(16 * 40 * 2) + ko);
        ldsm_x4(b,      bK + ko);
        ldsm_x4(b + 4,  bK + (u32)(16 * 40 * 2) + ko);
        ldsm_x4(b + 8,  bK + (u32)(32 * 40 * 2) + ko);
        ldsm_x2(b + 12, bK + (u32)(48 * 40 * 2) + ko);
#pragma unroll
        for (int i = 0; i < 2; i++)
#pragma unroll
            for (int j = 0; j < 7; j++)
                mma16(S[i][j], a[i], b + 2 * j);
    }

    const float scale = 0.17677669529663687f;
    const float4* tb = g_bias4 + (((tt * 6 + h) * 2 + (w & 1)) * 2) * 224;
    float rinv[2][2];
#pragma unroll
    for (int i = 0; i < 2; i++) {
        float rs0 = 0.f, rs1 = 0.f;
#pragma unroll
        for (int j = 0; j < 7; j++) {
            float4 tv = __ldg(&tb[(i * 7 + j) * 32 + lane]);
            float e0 = __expf(fmaf(S[i][j][0], scale, tv.x));
            float e1 = __expf(fmaf(S[i][j][1], scale, tv.y));
            float e2 = __expf(fmaf(S[i][j][2], scale, tv.z));
            float e3 = __expf(fmaf(S[i][j][3], scale, tv.w));
            S[i][j][0] = e0; S[i][j][1] = e1; S[i][j][2] = e2; S[i][j][3] = e3;
            rs0 += e0 + e1; rs1 += e2 + e3;
        }
        rs0 += __shfl_xor_sync(0xffffffffu, rs0, 1);
        rs0 += __shfl_xor_sync(0xffffffffu, rs0, 2);
        rs1 += __shfl_xor_sync(0xffffffffu, rs1, 1);
        rs1 += __shfl_xor_sync(0xffffffffu, rs1, 2);
        rinv[i][0] = 1.f / rs0;
        rinv[i][1] = 1.f / rs1;
    }

    float O[2][4][4] = {};
    const u32 bV = uVt + (u32)(((h * 32 + rb) * 72 + kbo) * 2);
#pragma unroll
    for (int kk = 0; kk < 4; kk++) {
        u32 a[2][4], b[8];
#pragma unroll
        for (int i = 0; i < 2; i++) {
            int j0 = 2 * kk, j1 = 2 * kk + 1;
            half2 h0 = __floats2half2_rn(S[i][j0][0], S[i][j0][1]);
            half2 h1 = __floats2half2_rn(S[i][j0][2], S[i][j0][3]);
            a[i][0] = *(const u32*)&h0;
            a[i][1] = *(const u32*)&h1;
            if (j1 < 7) {
                half2 h2 = __floats2half2_rn(S[i][j1][0], S[i][j1][1]);
                half2 h3 = __floats2half2_rn(S[i][j1][2], S[i][j1][3]);
                a[i][2] = *(const u32*)&h2;
                a[i][3] = *(const u32*)&h3;
            } else {
                a[i][2] = 0u; a[i][3] = 0u;
            }
        }
        const u32 ko = (u32)(kk * 32);
        ldsm_x4(b,     bV + ko);
        ldsm_x4(b + 4, bV + (u32)(16 * 72 * 2) + ko);
#pragma unroll
        for (int i = 0; i < 2; i++)
#pragma unroll
            for (int j = 0; j < 4; j++)
                mma16h(O[i][j], a[i], b + 2 * j);
    }

    bf16* dst0 = g_att + (size_t)bw * NTOK * DIM + h * 32;
#pragma unroll
    for (int i = 0; i < 2; i++)
#pragma unroll
        for (int half = 0; half < 2; half++) {
            int m = mbase + 16 * i + g + 8 * half;
            if (m < NTOK) {
                float inv = rinv[i][half];
                bf16* dp = dst0 + (size_t)m * DIM + 2 * tg;
#pragma unroll
                for (int j = 0; j < 4; j++) {
                    bf162 bb = __float22bfloat162_rn(
                        make_float2(O[i][j][2 * half] * inv, O[i][j][2 * half + 1] * inv));
                    *(bf162*)(dp + 8 * j) = bb;
                }
            }
        }
}

// ---------------- launcher ----------------
extern "C" void kernel_launch(void* const* d_in, const int* in_sizes, int n_in,
                              void* d_out, int out_size) {
    int base = (n_in >= 16) ? 3 : 1;
    const float* x      = (const float*)d_in[0];
    const float* qkv_w  = (const float*)d_in[base + 0];
    const float* qkv_b  = (const float*)d_in[base + 1];
    const float* proj_w = (const float*)d_in[base + 2];
    const float* proj_b = (const float*)d_in[base + 3];
    const float* rpb    = (const float*)d_in[base + 4];
    const float* n1w    = (const float*)d_in[base + 5];
    const float* n1b    = (const float*)d_in[base + 6];
    const float* n2w    = (const float*)d_in[base + 7];
    const float* n2b    = (const float*)d_in[base + 8];
    const float* w1     = (const float*)d_in[base + 9];
    const float* b1     = (const float*)d_in[base + 10];
    const float* w2     = (const float*)d_in[base + 11];
    const float* b2     = (const float*)d_in[base + 12];
    float* out = (float*)d_out;

    cudaFuncSetAttribute(k_mma, cudaFuncAttributeMaxDynamicSharedMemorySize, MMA_SMEM);
    cudaFuncSetAttribute(k_proj, cudaFuncAttributeMaxDynamicSharedMemorySize, PRJ_SMEM);
    cudaFuncSetAttribute(k_mlp, cudaFuncAttributeMaxDynamicSharedMemorySize, MLP_SMEM);
    cudaFuncSetAttribute(k_attn, cudaFuncAttributeMaxDynamicSharedMemorySize, ATT_SMEM);

    bf16* g_wt_p;
    cudaGetSymbolAddress((void**)&g_wt_p, g_wt);

    const int nblk_ln = MTOK / 8;
    const int mt = MTOK / 128;         // 3136

    // 0. weight transposes + bias/mask tables
    k_trall<<<1728, 256>>>(qkv_w, proj_w, w1, w2, g_wt_p);
    k_bias4<<<(21504 + 255) / 256, 256>>>(rpb);
    // 1. LN1 + shifted-window gather -> g_h (bf16)
    k_ln<<<nblk_ln, 256>>>(x, n1w, n1b);
    // 2. QKV GEMM -> g_qkv (bf16), persistent CTAs, resident B
    k_mma<<<294, 256, MMA_SMEM>>>(g_wt_p + WT_QKV, qkv_b);
    // 3. tensor-core window attention -> g_att (bf16)
    k_attn<<<NWTOT, 384, ATT_SMEM>>>();
    // 4. fused proj + residual + LN2 -> g_y (fp32), g_h (bf16), persistent
    k_proj<<<296, 256, PRJ_SMEM>>>(g_wt_p + WT_PRJ, proj_b, x, n2w, n2b);
    // 5+6. fused MLP + residual -> d_out
    k_mlp<<<mt, 512, MLP_SMEM>>>(g_wt_p + WT_M1, g_wt_p + WT_M2, b1, b2, out);
}